// round 13
// baseline (speedup 1.0000x reference)
#include <cuda_runtime.h>
#include <cuda_bf16.h>
#include <math.h>
#include <stdint.h>

typedef __nv_bfloat16 bf16;

#define B_   2
#define S_   512
#define T_   1024
#define D_   1280
#define H_   20
#define L_   16
#define DI_  2560
#define W1O_ 5120
#define OUT_PER_B 5242880

// ---------------- PTX helpers (baseline, non-'a' features only) ----------------
__device__ __forceinline__ uint32_t smem_u32(const void* p) {
    uint32_t a;
    asm("{ .reg .u64 t; cvta.to.shared.u64 t, %1; cvt.u32.u64 %0, t; }" : "=r"(a) : "l"(p));
    return a;
}
#define SWZ(o) ((o) ^ (((o) >> 3) & 0x70))

#define CPASYNC(dst, src) \
    asm volatile("cp.async.cg.shared.global [%0], [%1], 16;" :: "r"(dst), "l"(src))
#define CPCOMMIT() asm volatile("cp.async.commit_group;" ::: "memory")
#define CPWAIT1()  asm volatile("cp.async.wait_group 1;" ::: "memory")
#define CPWAIT0()  asm volatile("cp.async.wait_group 0;" ::: "memory")

__device__ __forceinline__ void ldsm4(uint32_t* r, uint32_t addr) {
    asm volatile("ldmatrix.sync.aligned.m8n8.x4.shared.b16 {%0,%1,%2,%3}, [%4];"
        : "=r"(r[0]), "=r"(r[1]), "=r"(r[2]), "=r"(r[3]) : "r"(addr));
}
__device__ __forceinline__ uint32_t lds32(uint32_t addr) {
    uint32_t v;
    asm volatile("ld.shared.b32 %0, [%1];" : "=r"(v) : "r"(addr));
    return v;
}
__device__ __forceinline__ void mma_bf16(float* d, const uint32_t* a, const uint32_t* b) {
    asm volatile(
        "mma.sync.aligned.m16n8k16.row.col.f32.bf16.bf16.f32 "
        "{%0,%1,%2,%3}, {%4,%5,%6,%7}, {%8,%9}, {%0,%1,%2,%3};"
        : "+f"(d[0]), "+f"(d[1]), "+f"(d[2]), "+f"(d[3])
        : "r"(a[0]), "r"(a[1]), "r"(a[2]), "r"(a[3]), "r"(b[0]), "r"(b[1]));
}

// ---------------- scratch (bf16 arena) ----------------
#define O_QKVT_H 0ll
#define O_QKVT_L 78643200ll
#define O_WOT_H  157286400ll
#define O_WOT_L  183500800ll
#define O_W1T_H  209715200ll
#define O_W1T_L  314572800ll
#define O_W2T_H  419430400ll
#define O_W2T_L  471859200ll
#define O_CLST_H 524288000ll
#define O_CLST_L 537395200ll
#define O_H_H    550502400ll
#define O_H_L    551813120ll
#define O_QKV_H  553123840ll
#define O_QKV_L  557056000ll
#define O_VT_H   560988160ll
#define O_VT_L   562331648ll
#define O_ATT_H  563675136ll
#define O_ATT_L  574160896ll
#define O_O_H    584646656ll
#define O_O_L    585957376ll
#define O_XS_H   587268096ll
#define O_XS_L   588578816ll
#define O_G_H    589889536ll
#define O_G_L    592510976ll
__device__ bf16 g_bf[595132416ll];
#define OF_X 0
#define OF_S 6553600
__device__ float g_f[17039360];

// ---------------- small kernels ----------------
__global__ void embed_kernel(const float* __restrict__ lat, const float* __restrict__ ew,
                             const float* __restrict__ eb, float* __restrict__ x) {
    int t = blockIdx.y, d = blockIdx.x * 256 + threadIdx.x;
    __shared__ float l[112];
    int b = t >> 9, n = t & 511;
    if (threadIdx.x < 112) l[threadIdx.x] = lat[(size_t)b * 57344 + threadIdx.x * 512 + n];
    __syncthreads();
    float s = eb[d];
    const float* w = ew + (size_t)d * 112;
#pragma unroll 8
    for (int c = 0; c < 112; c++) s += l[c] * w[c];
    x[(size_t)t * D_ + d] = s;
}

__device__ __forceinline__ void spst(float v, bf16* hi, bf16* lo, size_t i) {
    bf16 h = __float2bfloat16(v);
    hi[i] = h;
    lo[i] = __float2bfloat16(v - __bfloat162float(h));
}

__global__ __launch_bounds__(256) void rmsnorm_kernel(const float* __restrict__ x,
                                                      const float* __restrict__ w,
                                                      bf16* __restrict__ oh, bf16* __restrict__ ol) {
    int t = blockIdx.x;
    const float* xr = x + (size_t)t * D_;
    float ss = 0.f;
    for (int i = threadIdx.x; i < D_; i += 256) { float v = xr[i]; ss += v * v; }
    __shared__ float red[8];
    float v = ss;
#pragma unroll
    for (int o = 16; o; o >>= 1) v += __shfl_down_sync(~0u, v, o);
    if ((threadIdx.x & 31) == 0) red[threadIdx.x >> 5] = v;
    __syncthreads();
    if (threadIdx.x == 0) { float r = 0.f; for (int i = 0; i < 8; i++) r += red[i]; red[0] = r; }
    __syncthreads();
    float inv = rsqrtf(red[0] / (float)D_ + 1e-5f);
    size_t b = (size_t)t * D_;
    for (int i = threadIdx.x; i < D_; i += 256) spst(w[i] * (xr[i] * inv), oh, ol, b + i);
}

__device__ __forceinline__ float relbias(const float* __restrict__ rb, int i, int j, int h) {
    int n = i - j, ret = (n < 0) ? 16 : 0, an = (n < 0) ? -n : n, val;
    if (an < 8) val = an;
    else { val = 8 + (int)(logf((float)an * 0.125f) * (8.0f / logf(16.0f))); if (val > 15) val = 15; }
    return rb[(ret + val) * H_ + h];
}

__global__ __launch_bounds__(256) void softmax_kernel(const float* __restrict__ sc,
                                                      const float* __restrict__ rb,
                                                      bf16* __restrict__ ah, bf16* __restrict__ al,
                                                      int add_bias) {
    int i = blockIdx.x, bh = blockIdx.y, h = bh % H_, tid = threadIdx.x;
    const float* p = sc + ((size_t)bh * S_ + i) * S_;
    float v0 = p[tid], v1 = p[tid + 256];
    if (add_bias) { v0 += relbias(rb, i, tid, h); v1 += relbias(rb, i, tid + 256, h); }
    float m = fmaxf(v0, v1);
    __shared__ float rm[8], rs[8];
#pragma unroll
    for (int o = 16; o; o >>= 1) m = fmaxf(m, __shfl_down_sync(~0u, m, o));
    if ((tid & 31) == 0) rm[tid >> 5] = m;
    __syncthreads();
    if (tid == 0) { float mm = rm[0]; for (int k = 1; k < 8; k++) mm = fmaxf(mm, rm[k]); rm[0] = mm; }
    __syncthreads();
    float bm = rm[0], e0 = expf(v0 - bm), e1 = expf(v1 - bm), s = e0 + e1;
#pragma unroll
    for (int o = 16; o; o >>= 1) s += __shfl_down_sync(~0u, s, o);
    if ((tid & 31) == 0) rs[tid >> 5] = s;
    __syncthreads();
    if (tid == 0) { float t = 0.f; for (int k = 0; k < 8; k++) t += rs[k]; rs[0] = t; }
    __syncthreads();
    float inv = 1.0f / rs[0];
    size_t ob = ((size_t)bh * S_ + i) * S_;
    spst(e0 * inv, ah, al, ob + tid);
    spst(e1 * inv, ah, al, ob + tid + 256);
}

// vectorized fp32 -> split bf16 (uint2 stores)
__global__ void split_kernel(const float* __restrict__ s, bf16* __restrict__ hi, bf16* __restrict__ lo) {
    int i = (blockIdx.x * 256 + threadIdx.x) << 2;
    float4 v = *(const float4*)(s + i);
    bf16 h4[4], l4[4];
    float vv[4] = {v.x, v.y, v.z, v.w};
#pragma unroll
    for (int j = 0; j < 4; j++) {
        bf16 h = __float2bfloat16(vv[j]);
        h4[j] = h;
        l4[j] = __float2bfloat16(vv[j] - __bfloat162float(h));
    }
    *(uint2*)(hi + i) = *(uint2*)h4;
    *(uint2*)(lo + i) = *(uint2*)l4;
}

// transpose+split (vectorized): src fp32 [K][N] (z-batched) -> dst bf16 [N][K] hi/lo.
// tile 64k x 32n; each thread stores 8 contiguous bf16 (uint4) per array.
// di>0: interleave row perm for fused GEGLU (a_j -> 2j, g_j -> 2j+1).
__global__ __launch_bounds__(256) void trans_split(const float* __restrict__ src, long long sZ,
                                                   int K, int N,
                                                   bf16* __restrict__ dh, bf16* __restrict__ dl,
                                                   long long dZ, int di) {
    __shared__ float t[64][33];
    int n0 = blockIdx.x * 32, k0 = blockIdx.y * 64;
    const float* s = src + (size_t)blockIdx.z * sZ;
    int c = threadIdx.x & 31, r0 = threadIdx.x >> 5;
#pragma unroll
    for (int i = 0; i < 8; i++)
        t[r0 + i * 8][c] = s[(size_t)(k0 + r0 + i * 8) * N + n0 + c];
    __syncthreads();
    int n_i = threadIdx.x >> 3, kg = threadIdx.x & 7;
    int n = n0 + n_i;
    int nr = di ? ((n < di) ? 2 * n : 2 * (n - di) + 1) : n;
    size_t base = (size_t)blockIdx.z * dZ + (size_t)nr * K + k0 + kg * 8;
    bf16 h8[8], l8[8];
#pragma unroll
    for (int j = 0; j < 8; j++) {
        float v = t[kg * 8 + j][n_i];
        bf16 h = __float2bfloat16(v);
        h8[j] = h;
        l8[j] = __float2bfloat16(v - __bfloat162float(h));
    }
    *(uint4*)(dh + base) = *(uint4*)h8;
    *(uint4*)(dl + base) = *(uint4*)l8;
}

// v transpose: qkv split [t][3840] (v at col 2560+h*64) -> vt[bh][64][512]
__global__ __launch_bounds__(256) void vtrans_kernel(const bf16* __restrict__ vh, const bf16* __restrict__ vl,
                                                     bf16* __restrict__ th_, bf16* __restrict__ tl_) {
    __shared__ bf16 th[32][72], tl[32][72];
    int tid = threadIdx.x, bh = blockIdx.y, b = bh / H_, h = bh - b * H_;
    int s0 = blockIdx.x * 32;
    size_t sb = (size_t)(b * S_ + s0) * 3840 + 2560 + h * 64;
    int r = tid >> 3, c8 = (tid & 7) * 8;
    *(uint4*)&th[r][c8] = *(const uint4*)(vh + sb + (size_t)r * 3840 + c8);
    *(uint4*)&tl[r][c8] = *(const uint4*)(vl + sb + (size_t)r * 3840 + c8);
    __syncthreads();
    int dk = tid >> 2, s4 = (tid & 3) * 8;
    bf16 oh[8], ol[8];
#pragma unroll
    for (int i = 0; i < 8; i++) { oh[i] = th[s4 + i][dk]; ol[i] = tl[s4 + i][dk]; }
    size_t db = ((size_t)bh * 64 + dk) * 512 + s0 + s4;
    *(uint4*)(th_ + db) = *(uint4*)oh;
    *(uint4*)(tl_ + db) = *(uint4*)ol;
}

// ---------------- split-bf16 HMMA GEMM (mma.sync m16n8k16) ----------------
// CTA tile BMxBN, K-block 64, 2-stage cp.async pipeline (R7/R9-proven structure,
// scalar LDS for B fragments — ldmatrix-B regressed twice, do not reintroduce).
// MMA inner loop is pass-outer (hh/hl/lh) so consecutive MMAs hit different
// accumulators; per-accumulator op order unchanged -> bitwise identical.
// BM=128: 256 thr, 8 warps (1 CTA/SM). BM=64: 128 thr, 4 warps (3 CTAs/SM).
// EPI: 0=f32*alpha, 1=split bf16, 2=f32 residual +=, 3=classifier scatter,
//      4=residual += AND split-store, 5=fused GEGLU split-store (interleaved a/g cols)
template <int BM, int BN, int EPI>
__global__ __launch_bounds__((BM == 128 ? 256 : 128), (BM == 128 ? 1 : 3)) void hgemm(
    const bf16* __restrict__ Ah, const bf16* __restrict__ Al, long long lda, long long aS1, long long aS2,
    const bf16* __restrict__ Bh, const bf16* __restrict__ Bl, long long ldb, long long bS1, long long bS2,
    int K, int zdiv, float alpha,
    float* __restrict__ Cf, bf16* __restrict__ Ch, bf16* __restrict__ Cl,
    long long ldc, long long cS1, long long cS2, const float* __restrict__ bias) {
    extern __shared__ char sm[];
    constexpr int NT = (BM == 128 ? 256 : 128);
    constexpr int WN_CNT = NT / 64;            // 4 or 2
    constexpr int WN = BN / WN_CNT;            // warp n extent (32 both)
    constexpr int MI = BM / 32;                // m16 tiles per warp (4 or 2)
    constexpr int NREG = WN / 8;               // n8 tiles per warp (4)
    constexpr int RPI = NT / 8;                // rows loaded per iter (32 or 16)
    constexpr int AT = BM * 128;               // A tile bytes
    constexpr int BT = BN * 128;               // B tile bytes
    constexpr int STG = 2 * AT + 2 * BT;

    const int tid = threadIdx.x, lane = tid & 31, wid = tid >> 5;
    const int wm = wid & 1, wn = wid >> 1;
    const int zq = blockIdx.z / zdiv, zr = blockIdx.z - zq * zdiv;
    const int m0 = blockIdx.y * BM, n0 = blockIdx.x * BN;
    const bf16* Ahp = Ah + zq * aS1 + zr * aS2 + (size_t)m0 * lda;
    const bf16* Alp = Al + zq * aS1 + zr * aS2 + (size_t)m0 * lda;
    const bf16* Bhp = Bh + zq * bS1 + zr * bS2 + (size_t)n0 * ldb;
    const bf16* Blp = Bl + zq * bS1 + zr * bS2 + (size_t)n0 * ldb;
    const uint32_t sbase = smem_u32(sm);
    const int KB = K >> 6;

    float acc[MI][NREG][4];
#pragma unroll
    for (int a = 0; a < MI; a++)
#pragma unroll
        for (int b = 0; b < NREG; b++)
#pragma unroll
            for (int c = 0; c < 4; c++) acc[a][b][c] = 0.f;

    const int lr = tid >> 3, lc = tid & 7;

#define LOAD_STAGE(st, kb) do { \
    uint32_t bse = sbase + (st) * STG; \
    long long ko = (long long)(kb) * 64; \
    _Pragma("unroll") \
    for (int i = 0; i < BM / RPI; i++) { \
        int r = lr + i * RPI; \
        uint32_t so = SWZ(r * 128 + lc * 16); \
        CPASYNC(bse + so,      Ahp + (size_t)r * lda + ko + lc * 8); \
        CPASYNC(bse + AT + so, Alp + (size_t)r * lda + ko + lc * 8); \
    } \
    _Pragma("unroll") \
    for (int i = 0; i < BN / RPI; i++) { \
        int r = lr + i * RPI; \
        uint32_t so = SWZ(r * 128 + lc * 16); \
        CPASYNC(bse + 2 * AT + so,      Bhp + (size_t)r * ldb + ko + lc * 8); \
        CPASYNC(bse + 2 * AT + BT + so, Blp + (size_t)r * ldb + ko + lc * 8); \
    } \
    CPCOMMIT(); \
} while (0)

    LOAD_STAGE(0, 0);
    if (KB > 1) LOAD_STAGE(1, 1);

    const int g = lane >> 2, t4 = lane & 3;
    const int arow = wm * (BM / 2) + (lane & 15);
    const int acolb = (lane >> 4) * 16;

    for (int kb = 0; kb < KB; kb++) {
        if (kb + 2 <= KB) CPWAIT1(); else CPWAIT0();
        __syncthreads();
        uint32_t sAh = sbase + (kb & 1) * STG;
        uint32_t sAl = sAh + AT, sBh = sAh + 2 * AT, sBl = sBh + BT;
#pragma unroll
        for (int ks = 0; ks < 4; ks++) {
            uint32_t aH[MI][4], aL[MI][4], bH[NREG][2], bL[NREG][2];
#pragma unroll
            for (int mi = 0; mi < MI; mi++) {
                uint32_t off = SWZ((arow + mi * 16) * 128 + ks * 32 + acolb);
                ldsm4(aH[mi], sAh + off);
                ldsm4(aL[mi], sAl + off);
            }
#pragma unroll
            for (int ni = 0; ni < NREG; ni++) {
                int row = wn * WN + ni * 8 + g;
                uint32_t o0 = SWZ(row * 128 + ks * 32 + t4 * 4);
                uint32_t o1 = SWZ(row * 128 + ks * 32 + t4 * 4 + 16);
                bH[ni][0] = lds32(sBh + o0); bH[ni][1] = lds32(sBh + o1);
                bL[ni][0] = lds32(sBl + o0); bL[ni][1] = lds32(sBl + o1);
            }
            // pass-outer: consecutive MMAs target different accumulators (ILP);
            // per-acc order is still hh, hl, lh -> bitwise identical results
#pragma unroll
            for (int p = 0; p < 3; p++)
#pragma unroll
                for (int mi = 0; mi < MI; mi++)
#pragma unroll
                    for (int ni = 0; ni < NREG; ni++)
                        mma_bf16(acc[mi][ni],
                                 (p == 2) ? aL[mi] : aH[mi],
                                 (p == 1) ? bL[ni] : bH[ni]);
        }
        __syncthreads();
        if (kb + 2 < KB) LOAD_STAGE(kb & 1, kb + 2);
    }
#undef LOAD_STAGE

    // epilogue
    const long long coff = zq * cS1 + zr * cS2;
#pragma unroll
    for (int mi = 0; mi < MI; mi++) {
        int r0 = m0 + wm * (BM / 2) + mi * 16 + g;
        int r1 = r0 + 8;
#pragma unroll
        for (int ni = 0; ni < NREG; ni++) {
            int col = n0 + wn * WN + ni * 8 + t4 * 2;
            float v0 = acc[mi][ni][0], v1 = acc[mi][ni][1];
            float v2 = acc[mi][ni][2], v3 = acc[mi][ni][3];
            if (EPI == 0) {
                float2 p0 = {v0 * alpha, v1 * alpha}, p1 = {v2 * alpha, v3 * alpha};
                *(float2*)(Cf + coff + (size_t)r0 * ldc + col) = p0;
                *(float2*)(Cf + coff + (size_t)r1 * ldc + col) = p1;
            } else if (EPI == 1) {
                size_t i0 = coff + (size_t)r0 * ldc + col;
                size_t i1 = coff + (size_t)r1 * ldc + col;
                bf16 h0 = __float2bfloat16(v0), h1 = __float2bfloat16(v1);
                bf16 h2 = __float2bfloat16(v2), h3 = __float2bfloat16(v3);
                __nv_bfloat162 hh0; hh0.x = h0; hh0.y = h1;
                __nv_bfloat162 hh1; hh1.x = h2; hh1.y = h3;
                *(__nv_bfloat162*)(Ch + i0) = hh0;
                *(__nv_bfloat162*)(Ch + i1) = hh1;
                __nv_bfloat162 ll0, ll1;
                ll0.x = __float2bfloat16(v0 - __bfloat162float(h0));
                ll0.y = __float2bfloat16(v1 - __bfloat162float(h1));
                ll1.x = __float2bfloat16(v2 - __bfloat162float(h2));
                ll1.y = __float2bfloat16(v3 - __bfloat162float(h3));
                *(__nv_bfloat162*)(Cl + i0) = ll0;
                *(__nv_bfloat162*)(Cl + i1) = ll1;
            } else if (EPI == 2) {
                float* p0 = Cf + coff + (size_t)r0 * ldc + col;
                float* p1 = Cf + coff + (size_t)r1 * ldc + col;
                float2 c0 = *(float2*)p0, c1 = *(float2*)p1;
                c0.x += v0; c0.y += v1; c1.x += v2; c1.y += v3;
                *(float2*)p0 = c0; *(float2*)p1 = c1;
            } else if (EPI == 4) {
                size_t i0 = coff + (size_t)r0 * ldc + col;
                size_t i1 = coff + (size_t)r1 * ldc + col;
                float2 c0 = *(float2*)(Cf + i0), c1 = *(float2*)(Cf + i1);
                c0.x += v0; c0.y += v1; c1.x += v2; c1.y += v3;
                *(float2*)(Cf + i0) = c0; *(float2*)(Cf + i1) = c1;
                bf16 h0 = __float2bfloat16(c0.x), h1 = __float2bfloat16(c0.y);
                bf16 h2 = __float2bfloat16(c1.x), h3 = __float2bfloat16(c1.y);
                __nv_bfloat162 hh0; hh0.x = h0; hh0.y = h1;
                __nv_bfloat162 hh1; hh1.x = h2; hh1.y = h3;
                *(__nv_bfloat162*)(Ch + i0) = hh0;
                *(__nv_bfloat162*)(Ch + i1) = hh1;
                __nv_bfloat162 ll0, ll1;
                ll0.x = __float2bfloat16(c0.x - __bfloat162float(h0));
                ll0.y = __float2bfloat16(c0.y - __bfloat162float(h1));
                ll1.x = __float2bfloat16(c1.x - __bfloat162float(h2));
                ll1.y = __float2bfloat16(c1.y - __bfloat162float(h3));
                *(__nv_bfloat162*)(Cl + i0) = ll0;
                *(__nv_bfloat162*)(Cl + i1) = ll1;
            } else if (EPI == 5) {
                // fused GEGLU: col even = a_j, col odd = g_j, j = col/2
                int j = col >> 1;
                float t0 = tanhf(0.7978845608028654f * (v1 + 0.044715f * v1 * v1 * v1));
                float w0 = v0 * (0.5f * v1 * (1.0f + t0));
                float t1 = tanhf(0.7978845608028654f * (v3 + 0.044715f * v3 * v3 * v3));
                float w1v = v2 * (0.5f * v3 * (1.0f + t1));
                spst(w0, Ch, Cl, (size_t)r0 * ldc + j);
                spst(w1v, Ch, Cl, (size_t)r1 * ldc + j);
            } else {
                int b0 = r0 >> 9, s0 = r0 & 511, b1 = r1 >> 9, s1 = r1 & 511;
#pragma unroll
                for (int e = 0; e < 2; e++) {
                    int cc = col + e;
                    int vv = cc / 10, pp = cc - vv * 10;
                    float bv = bias[cc];
                    Cf[(size_t)b0 * OUT_PER_B + (size_t)vv * 5120 + s0 * 10 + pp] = (e ? v1 : v0) + bv;
                    Cf[(size_t)b1 * OUT_PER_B + (size_t)vv * 5120 + s1 * 10 + pp] = (e ? v3 : v2) + bv;
                }
            }
        }
    }
}

// ---------------- host ----------------
extern "C" void kernel_launch(void* const* d_in, const int* in_sizes, int n_in,
                              void* d_out, int out_size) {
    const float* latents  = (const float*)d_in[0];
    const float* emb_w    = (const float*)d_in[1];
    const float* emb_b    = (const float*)d_in[2];
    const float* norm_w   = (const float*)d_in[3];
    const float* wq       = (const float*)d_in[4];
    const float* wk       = (const float*)d_in[5];
    const float* wv       = (const float*)d_in[6];
    const float* wo       = (const float*)d_in[7];
    const float* w1       = (const float*)d_in[8];
    const float* w2       = (const float*)d_in[9];
    const float* rel_bias = (const float*)d_in[10];
    const float* now      = (const float*)d_in[11];
    const float* cls_w    = (const float*)d_in[12];
    const float* cls_b    = (const float*)d_in[13];
    float* out = (float*)d_out;

    bf16* bfp = nullptr; float* fp = nullptr;
    cudaGetSymbolAddress((void**)&bfp, g_bf);
    cudaGetSymbolAddress((void**)&fp, g_f);

    const int SM128 = 2 * (2 * 128 * 128 + 2 * 128 * 128);  // 131072
    const int SM64  = 2 * (2 * 64 * 128 + 2 * 64 * 128);    // 65536
    const int SM64_1STG = SM64 / 2;                          // 32768 (KB=1 kernels)
    cudaFuncSetAttribute(hgemm<128,128,1>, cudaFuncAttributeMaxDynamicSharedMemorySize, SM128);
    cudaFuncSetAttribute(hgemm<64,64,0>,   cudaFuncAttributeMaxDynamicSharedMemorySize, SM64);
    cudaFuncSetAttribute(hgemm<64,64,1>,   cudaFuncAttributeMaxDynamicSharedMemorySize, SM64);
    cudaFuncSetAttribute(hgemm<64,64,2>,   cudaFuncAttributeMaxDynamicSharedMemorySize, SM64);
    cudaFuncSetAttribute(hgemm<64,64,3>,   cudaFuncAttributeMaxDynamicSharedMemorySize, SM64);
    cudaFuncSetAttribute(hgemm<64,64,4>,   cudaFuncAttributeMaxDynamicSharedMemorySize, SM64);
    cudaFuncSetAttribute(hgemm<64,64,5>,   cudaFuncAttributeMaxDynamicSharedMemorySize, SM64);

    float* x  = fp + OF_X;
    float* sc = fp + OF_S;

    // weight prep: vectorized transpose [K][N] -> [N][K] + split hi/lo
    trans_split<<<dim3(40, 20, 16), 256>>>(wq, 1638400, 1280, 1280, bfp + O_QKVT_H,           bfp + O_QKVT_L,           4915200, 0);
    trans_split<<<dim3(40, 20, 16), 256>>>(wk, 1638400, 1280, 1280, bfp + O_QKVT_H + 1638400, bfp + O_QKVT_L + 1638400, 4915200, 0);
    trans_split<<<dim3(40, 20, 16), 256>>>(wv, 1638400, 1280, 1280, bfp + O_QKVT_H + 3276800, bfp + O_QKVT_L + 3276800, 4915200, 0);
    trans_split<<<dim3(40, 20, 16), 256>>>(wo, 1638400, 1280, 1280, bfp + O_WOT_H, bfp + O_WOT_L, 1638400, 0);
    trans_split<<<dim3(160, 20, 16), 256>>>(w1, 6553600, 1280, 5120, bfp + O_W1T_H, bfp + O_W1T_L, 6553600, DI_);
    trans_split<<<dim3(40, 40, 16), 256>>>(w2, 3276800, 2560, 1280, bfp + O_W2T_H, bfp + O_W2T_L, 3276800, 0);
    split_kernel<<<12800, 256>>>(cls_w, bfp + O_CLST_H, bfp + O_CLST_L);

    embed_kernel<<<dim3(5, 1024), 256>>>(latents, emb_w, emb_b, x);

    for (int l = 0; l < L_; l++) {
        rmsnorm_kernel<<<T_, 256>>>(x, norm_w + (size_t)l * D_, bfp + O_H_H, bfp + O_H_L);
        // QKV: [1024,1280] @ [3840,1280]^T -> split qkv, 128x128 tiles
        // (240 tiles util 0.81; half the L2 operand re-fetch of 64x64)
        hgemm<128,128,1><<<dim3(30, 8, 1), 256, SM128>>>(
            bfp + O_H_H, bfp + O_H_L, 1280, 0, 0,
            bfp + O_QKVT_H + (size_t)l * 4915200, bfp + O_QKVT_L + (size_t)l * 4915200, 1280, 0, 0,
            1280, 1, 1.f, nullptr, bfp + O_QKV_H, bfp + O_QKV_L, 3840, 0, 0, nullptr);
        vtrans_kernel<<<dim3(16, 40), 256>>>(bfp + O_QKV_H, bfp + O_QKV_L, bfp + O_VT_H, bfp + O_VT_L);
        // scores: per bh q[512,64] @ k[512,64]^T * 0.125 -> f32; 64x64, 32KB smem
        hgemm<64,64,0><<<dim3(8, 8, 40), 128, SM64_1STG>>>(
            bfp + O_QKV_H, bfp + O_QKV_L, 3840, 1966080, 64,
            bfp + O_QKV_H + 1280, bfp + O_QKV_L + 1280, 3840, 1966080, 64,
            64, 20, 0.125f, sc, nullptr, nullptr, 512, 5242880, 262144, nullptr);
        softmax_kernel<<<dim3(512, 40), 256>>>(sc, rel_bias, bfp + O_ATT_H, bfp + O_ATT_L, l == 0 ? 1 : 0);
        // AV: att[512,512] @ vt[64,512]^T -> o split, 64x64 tiles
        hgemm<64,64,1><<<dim3(1, 8, 40), 128, SM64>>>(
            bfp + O_ATT_H, bfp + O_ATT_L, 512, 5242880, 262144,
            bfp + O_VT_H, bfp + O_VT_L, 512, 655360, 32768,
            512, 20, 1.f, nullptr, bfp + O_O_H, bfp + O_O_L, 1280, 655360, 64, nullptr);
        // x += o @ woT, fused split-store -> xs, 64x64 tiles
        hgemm<64,64,4><<<dim3(20, 16, 1), 128, SM64>>>(
            bfp + O_O_H, bfp + O_O_L, 1280, 0, 0,
            bfp + O_WOT_H + (size_t)l * 1638400, bfp + O_WOT_L + (size_t)l * 1638400, 1280, 0, 0,
            1280, 1, 1.f, x, bfp + O_XS_H, bfp + O_XS_L, 1280, 0, 0, nullptr);
        // gate = geglu(x @ w1T) fused in epilogue (interleaved W1T), 64x64 tiles
        hgemm<64,64,5><<<dim3(80, 16, 1), 128, SM64>>>(
            bfp + O_XS_H, bfp + O_XS_L, 1280, 0, 0,
            bfp + O_W1T_H + (size_t)l * 6553600, bfp + O_W1T_L + (size_t)l * 6553600, 1280, 0, 0,
            1280, 1, 1.f, nullptr, bfp + O_G_H, bfp + O_G_L, 2560, 0, 0, nullptr);
        // x += g @ w2T, 64x64 tiles
        hgemm<64,64,2><<<dim3(20, 16, 1), 128, SM64>>>(
            bfp + O_G_H, bfp + O_G_L, 2560, 0, 0,
            bfp + O_W2T_H + (size_t)l * 3276800, bfp + O_W2T_L + (size_t)l * 3276800, 2560, 0, 0,
            2560, 1, 1.f, x, nullptr, nullptr, 1280, 0, 0, nullptr);
    }

    rmsnorm_kernel<<<T_, 256>>>(x, now, bfp + O_H_H, bfp + O_H_L);
    // classifier, 64x64 tiles
    hgemm<64,64,3><<<dim3(160, 16, 1), 128, SM64>>>(
        bfp + O_H_H, bfp + O_H_L, 1280, 0, 0,
        bfp + O_CLST_H, bfp + O_CLST_L, 1280, 0, 0,
        1280, 1, 1.f, out, nullptr, nullptr, 0, 0, 0, cls_b);
}

// round 14
// speedup vs baseline: 1.0027x; 1.0027x over previous
#include <cuda_runtime.h>
#include <cuda_bf16.h>
#include <math.h>
#include <stdint.h>

typedef __nv_bfloat16 bf16;

#define B_   2
#define S_   512
#define T_   1024
#define D_   1280
#define H_   20
#define L_   16
#define DI_  2560
#define W1O_ 5120
#define OUT_PER_B 5242880

// ---------------- PTX helpers (baseline, non-'a' features only) ----------------
__device__ __forceinline__ uint32_t smem_u32(const void* p) {
    uint32_t a;
    asm("{ .reg .u64 t; cvta.to.shared.u64 t, %1; cvt.u32.u64 %0, t; }" : "=r"(a) : "l"(p));
    return a;
}
#define SWZ(o) ((o) ^ (((o) >> 3) & 0x70))

#define CPASYNC(dst, src) \
    asm volatile("cp.async.cg.shared.global [%0], [%1], 16;" :: "r"(dst), "l"(src))
#define CPCOMMIT() asm volatile("cp.async.commit_group;" ::: "memory")
#define CPWAIT1()  asm volatile("cp.async.wait_group 1;" ::: "memory")
#define CPWAIT0()  asm volatile("cp.async.wait_group 0;" ::: "memory")

__device__ __forceinline__ void ldsm4(uint32_t* r, uint32_t addr) {
    asm volatile("ldmatrix.sync.aligned.m8n8.x4.shared.b16 {%0,%1,%2,%3}, [%4];"
        : "=r"(r[0]), "=r"(r[1]), "=r"(r[2]), "=r"(r[3]) : "r"(addr));
}
__device__ __forceinline__ uint32_t lds32(uint32_t addr) {
    uint32_t v;
    asm volatile("ld.shared.b32 %0, [%1];" : "=r"(v) : "r"(addr));
    return v;
}
__device__ __forceinline__ void mma_bf16(float* d, const uint32_t* a, const uint32_t* b) {
    asm volatile(
        "mma.sync.aligned.m16n8k16.row.col.f32.bf16.bf16.f32 "
        "{%0,%1,%2,%3}, {%4,%5,%6,%7}, {%8,%9}, {%0,%1,%2,%3};"
        : "+f"(d[0]), "+f"(d[1]), "+f"(d[2]), "+f"(d[3])
        : "r"(a[0]), "r"(a[1]), "r"(a[2]), "r"(a[3]), "r"(b[0]), "r"(b[1]));
}

// ---------------- scratch (bf16 arena) ----------------
#define O_QKVT_H 0ll
#define O_QKVT_L 78643200ll
#define O_WOT_H  157286400ll
#define O_WOT_L  183500800ll
#define O_W1T_H  209715200ll
#define O_W1T_L  314572800ll
#define O_W2T_H  419430400ll
#define O_W2T_L  471859200ll
#define O_CLST_H 524288000ll
#define O_CLST_L 537395200ll
#define O_H_H    550502400ll
#define O_H_L    551813120ll
#define O_QKV_H  553123840ll
#define O_QKV_L  557056000ll
#define O_VT_H   560988160ll
#define O_VT_L   562331648ll
#define O_ATT_H  563675136ll
#define O_ATT_L  574160896ll
#define O_O_H    584646656ll
#define O_O_L    585957376ll
#define O_XS_H   587268096ll
#define O_XS_L   588578816ll
#define O_G_H    589889536ll
#define O_G_L    592510976ll
__device__ bf16 g_bf[595132416ll];
#define OF_X 0
#define OF_S 6553600
__device__ float g_f[17039360];

// ---------------- small kernels ----------------
__global__ void embed_kernel(const float* __restrict__ lat, const float* __restrict__ ew,
                             const float* __restrict__ eb, float* __restrict__ x) {
    int t = blockIdx.y, d = blockIdx.x * 256 + threadIdx.x;
    __shared__ float l[112];
    int b = t >> 9, n = t & 511;
    if (threadIdx.x < 112) l[threadIdx.x] = lat[(size_t)b * 57344 + threadIdx.x * 512 + n];
    __syncthreads();
    float s = eb[d];
    const float* w = ew + (size_t)d * 112;
#pragma unroll 8
    for (int c = 0; c < 112; c++) s += l[c] * w[c];
    x[(size_t)t * D_ + d] = s;
}

__device__ __forceinline__ void spst(float v, bf16* hi, bf16* lo, size_t i) {
    bf16 h = __float2bfloat16(v);
    hi[i] = h;
    lo[i] = __float2bfloat16(v - __bfloat162float(h));
}

__global__ __launch_bounds__(256) void rmsnorm_kernel(const float* __restrict__ x,
                                                      const float* __restrict__ w,
                                                      bf16* __restrict__ oh, bf16* __restrict__ ol) {
    int t = blockIdx.x;
    const float* xr = x + (size_t)t * D_;
    float ss = 0.f;
    for (int i = threadIdx.x; i < D_; i += 256) { float v = xr[i]; ss += v * v; }
    __shared__ float red[8];
    float v = ss;
#pragma unroll
    for (int o = 16; o; o >>= 1) v += __shfl_down_sync(~0u, v, o);
    if ((threadIdx.x & 31) == 0) red[threadIdx.x >> 5] = v;
    __syncthreads();
    if (threadIdx.x == 0) { float r = 0.f; for (int i = 0; i < 8; i++) r += red[i]; red[0] = r; }
    __syncthreads();
    float inv = rsqrtf(red[0] / (float)D_ + 1e-5f);
    size_t b = (size_t)t * D_;
    for (int i = threadIdx.x; i < D_; i += 256) spst(w[i] * (xr[i] * inv), oh, ol, b + i);
}

__device__ __forceinline__ float relbias(const float* __restrict__ rb, int i, int j, int h) {
    int n = i - j, ret = (n < 0) ? 16 : 0, an = (n < 0) ? -n : n, val;
    if (an < 8) val = an;
    else { val = 8 + (int)(logf((float)an * 0.125f) * (8.0f / logf(16.0f))); if (val > 15) val = 15; }
    return rb[(ret + val) * H_ + h];
}

__global__ __launch_bounds__(256) void softmax_kernel(const float* __restrict__ sc,
                                                      const float* __restrict__ rb,
                                                      bf16* __restrict__ ah, bf16* __restrict__ al,
                                                      int add_bias) {
    int i = blockIdx.x, bh = blockIdx.y, h = bh % H_, tid = threadIdx.x;
    const float* p = sc + ((size_t)bh * S_ + i) * S_;
    float v0 = p[tid], v1 = p[tid + 256];
    if (add_bias) { v0 += relbias(rb, i, tid, h); v1 += relbias(rb, i, tid + 256, h); }
    float m = fmaxf(v0, v1);
    __shared__ float rm[8], rs[8];
#pragma unroll
    for (int o = 16; o; o >>= 1) m = fmaxf(m, __shfl_down_sync(~0u, m, o));
    if ((tid & 31) == 0) rm[tid >> 5] = m;
    __syncthreads();
    if (tid == 0) { float mm = rm[0]; for (int k = 1; k < 8; k++) mm = fmaxf(mm, rm[k]); rm[0] = mm; }
    __syncthreads();
    float bm = rm[0], e0 = expf(v0 - bm), e1 = expf(v1 - bm), s = e0 + e1;
#pragma unroll
    for (int o = 16; o; o >>= 1) s += __shfl_down_sync(~0u, s, o);
    if ((tid & 31) == 0) rs[tid >> 5] = s;
    __syncthreads();
    if (tid == 0) { float t = 0.f; for (int k = 0; k < 8; k++) t += rs[k]; rs[0] = t; }
    __syncthreads();
    float inv = 1.0f / rs[0];
    size_t ob = ((size_t)bh * S_ + i) * S_;
    spst(e0 * inv, ah, al, ob + tid);
    spst(e1 * inv, ah, al, ob + tid + 256);
}

// vectorized fp32 -> split bf16 (uint2 stores)
__global__ void split_kernel(const float* __restrict__ s, bf16* __restrict__ hi, bf16* __restrict__ lo) {
    int i = (blockIdx.x * 256 + threadIdx.x) << 2;
    float4 v = *(const float4*)(s + i);
    bf16 h4[4], l4[4];
    float vv[4] = {v.x, v.y, v.z, v.w};
#pragma unroll
    for (int j = 0; j < 4; j++) {
        bf16 h = __float2bfloat16(vv[j]);
        h4[j] = h;
        l4[j] = __float2bfloat16(vv[j] - __bfloat162float(h));
    }
    *(uint2*)(hi + i) = *(uint2*)h4;
    *(uint2*)(lo + i) = *(uint2*)l4;
}

// transpose+split (vectorized): src fp32 [K][N] (z-batched) -> dst bf16 [N][K] hi/lo.
// tile 64k x 32n; each thread stores 8 contiguous bf16 (uint4) per array.
// di>0: interleave row perm for fused GEGLU (a_j -> 2j, g_j -> 2j+1).
__global__ __launch_bounds__(256) void trans_split(const float* __restrict__ src, long long sZ,
                                                   int K, int N,
                                                   bf16* __restrict__ dh, bf16* __restrict__ dl,
                                                   long long dZ, int di) {
    __shared__ float t[64][33];
    int n0 = blockIdx.x * 32, k0 = blockIdx.y * 64;
    const float* s = src + (size_t)blockIdx.z * sZ;
    int c = threadIdx.x & 31, r0 = threadIdx.x >> 5;
#pragma unroll
    for (int i = 0; i < 8; i++)
        t[r0 + i * 8][c] = s[(size_t)(k0 + r0 + i * 8) * N + n0 + c];
    __syncthreads();
    int n_i = threadIdx.x >> 3, kg = threadIdx.x & 7;
    int n = n0 + n_i;
    int nr = di ? ((n < di) ? 2 * n : 2 * (n - di) + 1) : n;
    size_t base = (size_t)blockIdx.z * dZ + (size_t)nr * K + k0 + kg * 8;
    bf16 h8[8], l8[8];
#pragma unroll
    for (int j = 0; j < 8; j++) {
        float v = t[kg * 8 + j][n_i];
        bf16 h = __float2bfloat16(v);
        h8[j] = h;
        l8[j] = __float2bfloat16(v - __bfloat162float(h));
    }
    *(uint4*)(dh + base) = *(uint4*)h8;
    *(uint4*)(dl + base) = *(uint4*)l8;
}

// v transpose: qkv split [t][3840] (v at col 2560+h*64) -> vt[bh][64][512]
__global__ __launch_bounds__(256) void vtrans_kernel(const bf16* __restrict__ vh, const bf16* __restrict__ vl,
                                                     bf16* __restrict__ th_, bf16* __restrict__ tl_) {
    __shared__ bf16 th[32][72], tl[32][72];
    int tid = threadIdx.x, bh = blockIdx.y, b = bh / H_, h = bh - b * H_;
    int s0 = blockIdx.x * 32;
    size_t sb = (size_t)(b * S_ + s0) * 3840 + 2560 + h * 64;
    int r = tid >> 3, c8 = (tid & 7) * 8;
    *(uint4*)&th[r][c8] = *(const uint4*)(vh + sb + (size_t)r * 3840 + c8);
    *(uint4*)&tl[r][c8] = *(const uint4*)(vl + sb + (size_t)r * 3840 + c8);
    __syncthreads();
    int dk = tid >> 2, s4 = (tid & 3) * 8;
    bf16 oh[8], ol[8];
#pragma unroll
    for (int i = 0; i < 8; i++) { oh[i] = th[s4 + i][dk]; ol[i] = tl[s4 + i][dk]; }
    size_t db = ((size_t)bh * 64 + dk) * 512 + s0 + s4;
    *(uint4*)(th_ + db) = *(uint4*)oh;
    *(uint4*)(tl_ + db) = *(uint4*)ol;
}

// ---------------- split-bf16 HMMA GEMM (mma.sync m16n8k16) ----------------
// CTA tile BMxBN, K-block 64, 2-stage cp.async pipeline. R5-proven mainloop:
// scalar LDS for B fragments (ldmatrix-B regressed twice) and pass-inner MMA
// order hh/hl/lh per accumulator (pass-outer reorder regressed in R13).
// BM=128: 256 thr, 8 warps (1 CTA/SM). BM=64: 128 thr, 4 warps (3 CTAs/SM).
// EPI: 0=f32*alpha, 1=split bf16, 2=f32 residual +=, 3=classifier scatter,
//      4=residual += AND split-store, 5=fused GEGLU split-store (interleaved a/g cols)
template <int BM, int BN, int EPI>
__global__ __launch_bounds__((BM == 128 ? 256 : 128), (BM == 128 ? 1 : 3)) void hgemm(
    const bf16* __restrict__ Ah, const bf16* __restrict__ Al, long long lda, long long aS1, long long aS2,
    const bf16* __restrict__ Bh, const bf16* __restrict__ Bl, long long ldb, long long bS1, long long bS2,
    int K, int zdiv, float alpha,
    float* __restrict__ Cf, bf16* __restrict__ Ch, bf16* __restrict__ Cl,
    long long ldc, long long cS1, long long cS2, const float* __restrict__ bias) {
    extern __shared__ char sm[];
    constexpr int NT = (BM == 128 ? 256 : 128);
    constexpr int WN_CNT = NT / 64;            // 4 or 2
    constexpr int WN = BN / WN_CNT;            // warp n extent (32 both)
    constexpr int MI = BM / 32;                // m16 tiles per warp (4 or 2)
    constexpr int NREG = WN / 8;               // n8 tiles per warp (4)
    constexpr int RPI = NT / 8;                // rows loaded per iter (32 or 16)
    constexpr int AT = BM * 128;               // A tile bytes
    constexpr int BT = BN * 128;               // B tile bytes
    constexpr int STG = 2 * AT + 2 * BT;

    const int tid = threadIdx.x, lane = tid & 31, wid = tid >> 5;
    const int wm = wid & 1, wn = wid >> 1;
    const int zq = blockIdx.z / zdiv, zr = blockIdx.z - zq * zdiv;
    const int m0 = blockIdx.y * BM, n0 = blockIdx.x * BN;
    const bf16* Ahp = Ah + zq * aS1 + zr * aS2 + (size_t)m0 * lda;
    const bf16* Alp = Al + zq * aS1 + zr * aS2 + (size_t)m0 * lda;
    const bf16* Bhp = Bh + zq * bS1 + zr * bS2 + (size_t)n0 * ldb;
    const bf16* Blp = Bl + zq * bS1 + zr * bS2 + (size_t)n0 * ldb;
    const uint32_t sbase = smem_u32(sm);
    const int KB = K >> 6;

    float acc[MI][NREG][4];
#pragma unroll
    for (int a = 0; a < MI; a++)
#pragma unroll
        for (int b = 0; b < NREG; b++)
#pragma unroll
            for (int c = 0; c < 4; c++) acc[a][b][c] = 0.f;

    const int lr = tid >> 3, lc = tid & 7;

#define LOAD_STAGE(st, kb) do { \
    uint32_t bse = sbase + (st) * STG; \
    long long ko = (long long)(kb) * 64; \
    _Pragma("unroll") \
    for (int i = 0; i < BM / RPI; i++) { \
        int r = lr + i * RPI; \
        uint32_t so = SWZ(r * 128 + lc * 16); \
        CPASYNC(bse + so,      Ahp + (size_t)r * lda + ko + lc * 8); \
        CPASYNC(bse + AT + so, Alp + (size_t)r * lda + ko + lc * 8); \
    } \
    _Pragma("unroll") \
    for (int i = 0; i < BN / RPI; i++) { \
        int r = lr + i * RPI; \
        uint32_t so = SWZ(r * 128 + lc * 16); \
        CPASYNC(bse + 2 * AT + so,      Bhp + (size_t)r * ldb + ko + lc * 8); \
        CPASYNC(bse + 2 * AT + BT + so, Blp + (size_t)r * ldb + ko + lc * 8); \
    } \
    CPCOMMIT(); \
} while (0)

    LOAD_STAGE(0, 0);
    if (KB > 1) LOAD_STAGE(1, 1);

    const int g = lane >> 2, t4 = lane & 3;
    const int arow = wm * (BM / 2) + (lane & 15);
    const int acolb = (lane >> 4) * 16;

    for (int kb = 0; kb < KB; kb++) {
        if (kb + 2 <= KB) CPWAIT1(); else CPWAIT0();
        __syncthreads();
        uint32_t sAh = sbase + (kb & 1) * STG;
        uint32_t sAl = sAh + AT, sBh = sAh + 2 * AT, sBl = sBh + BT;
#pragma unroll
        for (int ks = 0; ks < 4; ks++) {
            uint32_t aH[MI][4], aL[MI][4], bH[NREG][2], bL[NREG][2];
#pragma unroll
            for (int mi = 0; mi < MI; mi++) {
                uint32_t off = SWZ((arow + mi * 16) * 128 + ks * 32 + acolb);
                ldsm4(aH[mi], sAh + off);
                ldsm4(aL[mi], sAl + off);
            }
#pragma unroll
            for (int ni = 0; ni < NREG; ni++) {
                int row = wn * WN + ni * 8 + g;
                uint32_t o0 = SWZ(row * 128 + ks * 32 + t4 * 4);
                uint32_t o1 = SWZ(row * 128 + ks * 32 + t4 * 4 + 16);
                bH[ni][0] = lds32(sBh + o0); bH[ni][1] = lds32(sBh + o1);
                bL[ni][0] = lds32(sBl + o0); bL[ni][1] = lds32(sBl + o1);
            }
#pragma unroll
            for (int mi = 0; mi < MI; mi++)
#pragma unroll
                for (int ni = 0; ni < NREG; ni++) {
                    mma_bf16(acc[mi][ni], aH[mi], bH[ni]);
                    mma_bf16(acc[mi][ni], aH[mi], bL[ni]);
                    mma_bf16(acc[mi][ni], aL[mi], bH[ni]);
                }
        }
        __syncthreads();
        if (kb + 2 < KB) LOAD_STAGE(kb & 1, kb + 2);
    }
#undef LOAD_STAGE

    // epilogue
    const long long coff = zq * cS1 + zr * cS2;
#pragma unroll
    for (int mi = 0; mi < MI; mi++) {
        int r0 = m0 + wm * (BM / 2) + mi * 16 + g;
        int r1 = r0 + 8;
#pragma unroll
        for (int ni = 0; ni < NREG; ni++) {
            int col = n0 + wn * WN + ni * 8 + t4 * 2;
            float v0 = acc[mi][ni][0], v1 = acc[mi][ni][1];
            float v2 = acc[mi][ni][2], v3 = acc[mi][ni][3];
            if (EPI == 0) {
                float2 p0 = {v0 * alpha, v1 * alpha}, p1 = {v2 * alpha, v3 * alpha};
                *(float2*)(Cf + coff + (size_t)r0 * ldc + col) = p0;
                *(float2*)(Cf + coff + (size_t)r1 * ldc + col) = p1;
            } else if (EPI == 1) {
                size_t i0 = coff + (size_t)r0 * ldc + col;
                size_t i1 = coff + (size_t)r1 * ldc + col;
                bf16 h0 = __float2bfloat16(v0), h1 = __float2bfloat16(v1);
                bf16 h2 = __float2bfloat16(v2), h3 = __float2bfloat16(v3);
                __nv_bfloat162 hh0; hh0.x = h0; hh0.y = h1;
                __nv_bfloat162 hh1; hh1.x = h2; hh1.y = h3;
                *(__nv_bfloat162*)(Ch + i0) = hh0;
                *(__nv_bfloat162*)(Ch + i1) = hh1;
                __nv_bfloat162 ll0, ll1;
                ll0.x = __float2bfloat16(v0 - __bfloat162float(h0));
                ll0.y = __float2bfloat16(v1 - __bfloat162float(h1));
                ll1.x = __float2bfloat16(v2 - __bfloat162float(h2));
                ll1.y = __float2bfloat16(v3 - __bfloat162float(h3));
                *(__nv_bfloat162*)(Cl + i0) = ll0;
                *(__nv_bfloat162*)(Cl + i1) = ll1;
            } else if (EPI == 2) {
                float* p0 = Cf + coff + (size_t)r0 * ldc + col;
                float* p1 = Cf + coff + (size_t)r1 * ldc + col;
                float2 c0 = *(float2*)p0, c1 = *(float2*)p1;
                c0.x += v0; c0.y += v1; c1.x += v2; c1.y += v3;
                *(float2*)p0 = c0; *(float2*)p1 = c1;
            } else if (EPI == 4) {
                size_t i0 = coff + (size_t)r0 * ldc + col;
                size_t i1 = coff + (size_t)r1 * ldc + col;
                float2 c0 = *(float2*)(Cf + i0), c1 = *(float2*)(Cf + i1);
                c0.x += v0; c0.y += v1; c1.x += v2; c1.y += v3;
                *(float2*)(Cf + i0) = c0; *(float2*)(Cf + i1) = c1;
                bf16 h0 = __float2bfloat16(c0.x), h1 = __float2bfloat16(c0.y);
                bf16 h2 = __float2bfloat16(c1.x), h3 = __float2bfloat16(c1.y);
                __nv_bfloat162 hh0; hh0.x = h0; hh0.y = h1;
                __nv_bfloat162 hh1; hh1.x = h2; hh1.y = h3;
                *(__nv_bfloat162*)(Ch + i0) = hh0;
                *(__nv_bfloat162*)(Ch + i1) = hh1;
                __nv_bfloat162 ll0, ll1;
                ll0.x = __float2bfloat16(c0.x - __bfloat162float(h0));
                ll0.y = __float2bfloat16(c0.y - __bfloat162float(h1));
                ll1.x = __float2bfloat16(c1.x - __bfloat162float(h2));
                ll1.y = __float2bfloat16(c1.y - __bfloat162float(h3));
                *(__nv_bfloat162*)(Cl + i0) = ll0;
                *(__nv_bfloat162*)(Cl + i1) = ll1;
            } else if (EPI == 5) {
                // fused GEGLU: col even = a_j, col odd = g_j, j = col/2
                int j = col >> 1;
                float t0 = tanhf(0.7978845608028654f * (v1 + 0.044715f * v1 * v1 * v1));
                float w0 = v0 * (0.5f * v1 * (1.0f + t0));
                float t1 = tanhf(0.7978845608028654f * (v3 + 0.044715f * v3 * v3 * v3));
                float w1v = v2 * (0.5f * v3 * (1.0f + t1));
                spst(w0, Ch, Cl, (size_t)r0 * ldc + j);
                spst(w1v, Ch, Cl, (size_t)r1 * ldc + j);
            } else {
                int b0 = r0 >> 9, s0 = r0 & 511, b1 = r1 >> 9, s1 = r1 & 511;
#pragma unroll
                for (int e = 0; e < 2; e++) {
                    int cc = col + e;
                    int vv = cc / 10, pp = cc - vv * 10;
                    float bv = bias[cc];
                    Cf[(size_t)b0 * OUT_PER_B + (size_t)vv * 5120 + s0 * 10 + pp] = (e ? v1 : v0) + bv;
                    Cf[(size_t)b1 * OUT_PER_B + (size_t)vv * 5120 + s1 * 10 + pp] = (e ? v3 : v2) + bv;
                }
            }
        }
    }
}

// ---------------- host ----------------
extern "C" void kernel_launch(void* const* d_in, const int* in_sizes, int n_in,
                              void* d_out, int out_size) {
    const float* latents  = (const float*)d_in[0];
    const float* emb_w    = (const float*)d_in[1];
    const float* emb_b    = (const float*)d_in[2];
    const float* norm_w   = (const float*)d_in[3];
    const float* wq       = (const float*)d_in[4];
    const float* wk       = (const float*)d_in[5];
    const float* wv       = (const float*)d_in[6];
    const float* wo       = (const float*)d_in[7];
    const float* w1       = (const float*)d_in[8];
    const float* w2       = (const float*)d_in[9];
    const float* rel_bias = (const float*)d_in[10];
    const float* now      = (const float*)d_in[11];
    const float* cls_w    = (const float*)d_in[12];
    const float* cls_b    = (const float*)d_in[13];
    float* out = (float*)d_out;

    bf16* bfp = nullptr; float* fp = nullptr;
    cudaGetSymbolAddress((void**)&bfp, g_bf);
    cudaGetSymbolAddress((void**)&fp, g_f);

    const int SM128 = 2 * (2 * 128 * 128 + 2 * 128 * 128);  // 131072
    const int SM64  = 2 * (2 * 64 * 128 + 2 * 64 * 128);    // 65536
    const int SM64_1STG = SM64 / 2;                          // 32768 (KB=1 kernels)
    cudaFuncSetAttribute(hgemm<128,128,1>, cudaFuncAttributeMaxDynamicSharedMemorySize, SM128);
    cudaFuncSetAttribute(hgemm<64,64,0>,   cudaFuncAttributeMaxDynamicSharedMemorySize, SM64);
    cudaFuncSetAttribute(hgemm<64,64,1>,   cudaFuncAttributeMaxDynamicSharedMemorySize, SM64);
    cudaFuncSetAttribute(hgemm<64,64,2>,   cudaFuncAttributeMaxDynamicSharedMemorySize, SM64);
    cudaFuncSetAttribute(hgemm<64,64,3>,   cudaFuncAttributeMaxDynamicSharedMemorySize, SM64);
    cudaFuncSetAttribute(hgemm<64,64,4>,   cudaFuncAttributeMaxDynamicSharedMemorySize, SM64);
    cudaFuncSetAttribute(hgemm<64,64,5>,   cudaFuncAttributeMaxDynamicSharedMemorySize, SM64);

    float* x  = fp + OF_X;
    float* sc = fp + OF_S;

    // weight prep: vectorized transpose [K][N] -> [N][K] + split hi/lo
    trans_split<<<dim3(40, 20, 16), 256>>>(wq, 1638400, 1280, 1280, bfp + O_QKVT_H,           bfp + O_QKVT_L,           4915200, 0);
    trans_split<<<dim3(40, 20, 16), 256>>>(wk, 1638400, 1280, 1280, bfp + O_QKVT_H + 1638400, bfp + O_QKVT_L + 1638400, 4915200, 0);
    trans_split<<<dim3(40, 20, 16), 256>>>(wv, 1638400, 1280, 1280, bfp + O_QKVT_H + 3276800, bfp + O_QKVT_L + 3276800, 4915200, 0);
    trans_split<<<dim3(40, 20, 16), 256>>>(wo, 1638400, 1280, 1280, bfp + O_WOT_H, bfp + O_WOT_L, 1638400, 0);
    trans_split<<<dim3(160, 20, 16), 256>>>(w1, 6553600, 1280, 5120, bfp + O_W1T_H, bfp + O_W1T_L, 6553600, DI_);
    trans_split<<<dim3(40, 40, 16), 256>>>(w2, 3276800, 2560, 1280, bfp + O_W2T_H, bfp + O_W2T_L, 3276800, 0);
    split_kernel<<<12800, 256>>>(cls_w, bfp + O_CLST_H, bfp + O_CLST_L);

    embed_kernel<<<dim3(5, 1024), 256>>>(latents, emb_w, emb_b, x);

    for (int l = 0; l < L_; l++) {
        rmsnorm_kernel<<<T_, 256>>>(x, norm_w + (size_t)l * D_, bfp + O_H_H, bfp + O_H_L);
        // QKV: [1024,1280] @ [3840,1280]^T -> split qkv, 128x128 tiles
        // (single change vs R12: 240 tiles util 0.81 vs 960/0.72, half L2 re-fetch)
        hgemm<128,128,1><<<dim3(30, 8, 1), 256, SM128>>>(
            bfp + O_H_H, bfp + O_H_L, 1280, 0, 0,
            bfp + O_QKVT_H + (size_t)l * 4915200, bfp + O_QKVT_L + (size_t)l * 4915200, 1280, 0, 0,
            1280, 1, 1.f, nullptr, bfp + O_QKV_H, bfp + O_QKV_L, 3840, 0, 0, nullptr);
        vtrans_kernel<<<dim3(16, 40), 256>>>(bfp + O_QKV_H, bfp + O_QKV_L, bfp + O_VT_H, bfp + O_VT_L);
        // scores: per bh q[512,64] @ k[512,64]^T * 0.125 -> f32; 64x64, 32KB smem
        hgemm<64,64,0><<<dim3(8, 8, 40), 128, SM64_1STG>>>(
            bfp + O_QKV_H, bfp + O_QKV_L, 3840, 1966080, 64,
            bfp + O_QKV_H + 1280, bfp + O_QKV_L + 1280, 3840, 1966080, 64,
            64, 20, 0.125f, sc, nullptr, nullptr, 512, 5242880, 262144, nullptr);
        softmax_kernel<<<dim3(512, 40), 256>>>(sc, rel_bias, bfp + O_ATT_H, bfp + O_ATT_L, l == 0 ? 1 : 0);
        // AV: att[512,512] @ vt[64,512]^T -> o split, 64x64 tiles
        hgemm<64,64,1><<<dim3(1, 8, 40), 128, SM64>>>(
            bfp + O_ATT_H, bfp + O_ATT_L, 512, 5242880, 262144,
            bfp + O_VT_H, bfp + O_VT_L, 512, 655360, 32768,
            512, 20, 1.f, nullptr, bfp + O_O_H, bfp + O_O_L, 1280, 655360, 64, nullptr);
        // x += o @ woT, fused split-store -> xs, 64x64 tiles
        hgemm<64,64,4><<<dim3(20, 16, 1), 128, SM64>>>(
            bfp + O_O_H, bfp + O_O_L, 1280, 0, 0,
            bfp + O_WOT_H + (size_t)l * 1638400, bfp + O_WOT_L + (size_t)l * 1638400, 1280, 0, 0,
            1280, 1, 1.f, x, bfp + O_XS_H, bfp + O_XS_L, 1280, 0, 0, nullptr);
        // gate = geglu(x @ w1T) fused in epilogue (interleaved W1T), 64x64 tiles
        hgemm<64,64,5><<<dim3(80, 16, 1), 128, SM64>>>(
            bfp + O_XS_H, bfp + O_XS_L, 1280, 0, 0,
            bfp + O_W1T_H + (size_t)l * 6553600, bfp + O_W1T_L + (size_t)l * 6553600, 1280, 0, 0,
            1280, 1, 1.f, nullptr, bfp + O_G_H, bfp + O_G_L, 2560, 0, 0, nullptr);
        // x += g @ w2T, 64x64 tiles
        hgemm<64,64,2><<<dim3(20, 16, 1), 128, SM64>>>(
            bfp + O_G_H, bfp + O_G_L, 2560, 0, 0,
            bfp + O_W2T_H + (size_t)l * 3276800, bfp + O_W2T_L + (size_t)l * 3276800, 2560, 0, 0,
            2560, 1, 1.f, x, nullptr, nullptr, 1280, 0, 0, nullptr);
    }

    rmsnorm_kernel<<<T_, 256>>>(x, now, bfp + O_H_H, bfp + O_H_L);
    // classifier, 64x64 tiles
    hgemm<64,64,3><<<dim3(160, 16, 1), 128, SM64>>>(
        bfp + O_H_H, bfp + O_H_L, 1280, 0, 0,
        bfp + O_CLST_H, bfp + O_CLST_L, 1280, 0, 0,
        1280, 1, 1.f, out, nullptr, nullptr, 0, 0, 0, cls_b);
}

// round 15
// speedup vs baseline: 1.0287x; 1.0259x over previous
#include <cuda_runtime.h>
#include <cuda_bf16.h>
#include <math.h>
#include <stdint.h>

typedef __nv_bfloat16 bf16;

#define B_   2
#define S_   512
#define T_   1024
#define D_   1280
#define H_   20
#define L_   16
#define DI_  2560
#define W1O_ 5120
#define OUT_PER_B 5242880

// ---------------- PTX helpers (baseline, non-'a' features only) ----------------
__device__ __forceinline__ uint32_t smem_u32(const void* p) {
    uint32_t a;
    asm("{ .reg .u64 t; cvta.to.shared.u64 t, %1; cvt.u32.u64 %0, t; }" : "=r"(a) : "l"(p));
    return a;
}
#define SWZ(o) ((o) ^ (((o) >> 3) & 0x70))

#define CPASYNC(dst, src) \
    asm volatile("cp.async.cg.shared.global [%0], [%1], 16;" :: "r"(dst), "l"(src))
#define CPCOMMIT() asm volatile("cp.async.commit_group;" ::: "memory")
#define CPWAIT1()  asm volatile("cp.async.wait_group 1;" ::: "memory")
#define CPWAIT0()  asm volatile("cp.async.wait_group 0;" ::: "memory")

__device__ __forceinline__ void ldsm4(uint32_t* r, uint32_t addr) {
    asm volatile("ldmatrix.sync.aligned.m8n8.x4.shared.b16 {%0,%1,%2,%3}, [%4];"
        : "=r"(r[0]), "=r"(r[1]), "=r"(r[2]), "=r"(r[3]) : "r"(addr));
}
__device__ __forceinline__ uint32_t lds32(uint32_t addr) {
    uint32_t v;
    asm volatile("ld.shared.b32 %0, [%1];" : "=r"(v) : "r"(addr));
    return v;
}
__device__ __forceinline__ void mma_bf16(float* d, const uint32_t* a, const uint32_t* b) {
    asm volatile(
        "mma.sync.aligned.m16n8k16.row.col.f32.bf16.bf16.f32 "
        "{%0,%1,%2,%3}, {%4,%5,%6,%7}, {%8,%9}, {%0,%1,%2,%3};"
        : "+f"(d[0]), "+f"(d[1]), "+f"(d[2]), "+f"(d[3])
        : "r"(a[0]), "r"(a[1]), "r"(a[2]), "r"(a[3]), "r"(b[0]), "r"(b[1]));
}

// ---------------- scratch (bf16 arena) ----------------
#define O_QKVT_H 0ll
#define O_QKVT_L 78643200ll
#define O_WOT_H  157286400ll
#define O_WOT_L  183500800ll
#define O_W1T_H  209715200ll
#define O_W1T_L  314572800ll
#define O_W2T_H  419430400ll
#define O_W2T_L  471859200ll
#define O_CLST_H 524288000ll
#define O_CLST_L 537395200ll
#define O_H_H    550502400ll
#define O_H_L    551813120ll
#define O_QKV_H  553123840ll
#define O_QKV_L  557056000ll
#define O_VT_H   560988160ll
#define O_VT_L   562331648ll
#define O_ATT_H  563675136ll
#define O_ATT_L  574160896ll
#define O_O_H    584646656ll
#define O_O_L    585957376ll
#define O_XS_H   587268096ll
#define O_XS_L   588578816ll
#define O_G_H    589889536ll
#define O_G_L    592510976ll
__device__ bf16 g_bf[595132416ll];
#define OF_X 0
#define OF_S 6553600
__device__ float g_f[17039360];

// ---------------- small kernels ----------------
__global__ void embed_kernel(const float* __restrict__ lat, const float* __restrict__ ew,
                             const float* __restrict__ eb, float* __restrict__ x) {
    int t = blockIdx.y, d = blockIdx.x * 256 + threadIdx.x;
    __shared__ float l[112];
    int b = t >> 9, n = t & 511;
    if (threadIdx.x < 112) l[threadIdx.x] = lat[(size_t)b * 57344 + threadIdx.x * 512 + n];
    __syncthreads();
    float s = eb[d];
    const float* w = ew + (size_t)d * 112;
#pragma unroll 8
    for (int c = 0; c < 112; c++) s += l[c] * w[c];
    x[(size_t)t * D_ + d] = s;
}

__device__ __forceinline__ void spst(float v, bf16* hi, bf16* lo, size_t i) {
    bf16 h = __float2bfloat16(v);
    hi[i] = h;
    lo[i] = __float2bfloat16(v - __bfloat162float(h));
}

__global__ __launch_bounds__(256) void rmsnorm_kernel(const float* __restrict__ x,
                                                      const float* __restrict__ w,
                                                      bf16* __restrict__ oh, bf16* __restrict__ ol) {
    int t = blockIdx.x;
    const float* xr = x + (size_t)t * D_;
    float ss = 0.f;
    for (int i = threadIdx.x; i < D_; i += 256) { float v = xr[i]; ss += v * v; }
    __shared__ float red[8];
    float v = ss;
#pragma unroll
    for (int o = 16; o; o >>= 1) v += __shfl_down_sync(~0u, v, o);
    if ((threadIdx.x & 31) == 0) red[threadIdx.x >> 5] = v;
    __syncthreads();
    if (threadIdx.x == 0) { float r = 0.f; for (int i = 0; i < 8; i++) r += red[i]; red[0] = r; }
    __syncthreads();
    float inv = rsqrtf(red[0] / (float)D_ + 1e-5f);
    size_t b = (size_t)t * D_;
    for (int i = threadIdx.x; i < D_; i += 256) spst(w[i] * (xr[i] * inv), oh, ol, b + i);
}

__device__ __forceinline__ float relbias(const float* __restrict__ rb, int i, int j, int h) {
    int n = i - j, ret = (n < 0) ? 16 : 0, an = (n < 0) ? -n : n, val;
    if (an < 8) val = an;
    else { val = 8 + (int)(logf((float)an * 0.125f) * (8.0f / logf(16.0f))); if (val > 15) val = 15; }
    return rb[(ret + val) * H_ + h];
}

__global__ __launch_bounds__(256) void softmax_kernel(const float* __restrict__ sc,
                                                      const float* __restrict__ rb,
                                                      bf16* __restrict__ ah, bf16* __restrict__ al,
                                                      int add_bias) {
    int i = blockIdx.x, bh = blockIdx.y, h = bh % H_, tid = threadIdx.x;
    const float* p = sc + ((size_t)bh * S_ + i) * S_;
    float v0 = p[tid], v1 = p[tid + 256];
    if (add_bias) { v0 += relbias(rb, i, tid, h); v1 += relbias(rb, i, tid + 256, h); }
    float m = fmaxf(v0, v1);
    __shared__ float rm[8], rs[8];
#pragma unroll
    for (int o = 16; o; o >>= 1) m = fmaxf(m, __shfl_down_sync(~0u, m, o));
    if ((tid & 31) == 0) rm[tid >> 5] = m;
    __syncthreads();
    if (tid == 0) { float mm = rm[0]; for (int k = 1; k < 8; k++) mm = fmaxf(mm, rm[k]); rm[0] = mm; }
    __syncthreads();
    float bm = rm[0], e0 = expf(v0 - bm), e1 = expf(v1 - bm), s = e0 + e1;
#pragma unroll
    for (int o = 16; o; o >>= 1) s += __shfl_down_sync(~0u, s, o);
    if ((tid & 31) == 0) rs[tid >> 5] = s;
    __syncthreads();
    if (tid == 0) { float t = 0.f; for (int k = 0; k < 8; k++) t += rs[k]; rs[0] = t; }
    __syncthreads();
    float inv = 1.0f / rs[0];
    size_t ob = ((size_t)bh * S_ + i) * S_;
    spst(e0 * inv, ah, al, ob + tid);
    spst(e1 * inv, ah, al, ob + tid + 256);
}

// vectorized fp32 -> split bf16 (uint2 stores)
__global__ void split_kernel(const float* __restrict__ s, bf16* __restrict__ hi, bf16* __restrict__ lo) {
    int i = (blockIdx.x * 256 + threadIdx.x) << 2;
    float4 v = *(const float4*)(s + i);
    bf16 h4[4], l4[4];
    float vv[4] = {v.x, v.y, v.z, v.w};
#pragma unroll
    for (int j = 0; j < 4; j++) {
        bf16 h = __float2bfloat16(vv[j]);
        h4[j] = h;
        l4[j] = __float2bfloat16(vv[j] - __bfloat162float(h));
    }
    *(uint2*)(hi + i) = *(uint2*)h4;
    *(uint2*)(lo + i) = *(uint2*)l4;
}

// transpose+split (vectorized): src fp32 [K][N] (z-batched) -> dst bf16 [N][K] hi/lo.
// tile 64k x 32n; each thread stores 8 contiguous bf16 (uint4) per array.
// di>0: interleave row perm for fused GEGLU (a_j -> 2j, g_j -> 2j+1).
__global__ __launch_bounds__(256) void trans_split(const float* __restrict__ src, long long sZ,
                                                   int K, int N,
                                                   bf16* __restrict__ dh, bf16* __restrict__ dl,
                                                   long long dZ, int di) {
    __shared__ float t[64][33];
    int n0 = blockIdx.x * 32, k0 = blockIdx.y * 64;
    const float* s = src + (size_t)blockIdx.z * sZ;
    int c = threadIdx.x & 31, r0 = threadIdx.x >> 5;
#pragma unroll
    for (int i = 0; i < 8; i++)
        t[r0 + i * 8][c] = s[(size_t)(k0 + r0 + i * 8) * N + n0 + c];
    __syncthreads();
    int n_i = threadIdx.x >> 3, kg = threadIdx.x & 7;
    int n = n0 + n_i;
    int nr = di ? ((n < di) ? 2 * n : 2 * (n - di) + 1) : n;
    size_t base = (size_t)blockIdx.z * dZ + (size_t)nr * K + k0 + kg * 8;
    bf16 h8[8], l8[8];
#pragma unroll
    for (int j = 0; j < 8; j++) {
        float v = t[kg * 8 + j][n_i];
        bf16 h = __float2bfloat16(v);
        h8[j] = h;
        l8[j] = __float2bfloat16(v - __bfloat162float(h));
    }
    *(uint4*)(dh + base) = *(uint4*)h8;
    *(uint4*)(dl + base) = *(uint4*)l8;
}

// v transpose: qkv split [t][3840] (v at col 2560+h*64) -> vt[bh][64][512]
__global__ __launch_bounds__(256) void vtrans_kernel(const bf16* __restrict__ vh, const bf16* __restrict__ vl,
                                                     bf16* __restrict__ th_, bf16* __restrict__ tl_) {
    __shared__ bf16 th[32][72], tl[32][72];
    int tid = threadIdx.x, bh = blockIdx.y, b = bh / H_, h = bh - b * H_;
    int s0 = blockIdx.x * 32;
    size_t sb = (size_t)(b * S_ + s0) * 3840 + 2560 + h * 64;
    int r = tid >> 3, c8 = (tid & 7) * 8;
    *(uint4*)&th[r][c8] = *(const uint4*)(vh + sb + (size_t)r * 3840 + c8);
    *(uint4*)&tl[r][c8] = *(const uint4*)(vl + sb + (size_t)r * 3840 + c8);
    __syncthreads();
    int dk = tid >> 2, s4 = (tid & 3) * 8;
    bf16 oh[8], ol[8];
#pragma unroll
    for (int i = 0; i < 8; i++) { oh[i] = th[s4 + i][dk]; ol[i] = tl[s4 + i][dk]; }
    size_t db = ((size_t)bh * 64 + dk) * 512 + s0 + s4;
    *(uint4*)(th_ + db) = *(uint4*)oh;
    *(uint4*)(tl_ + db) = *(uint4*)ol;
}

// ---------------- split-bf16 HMMA GEMM (mma.sync m16n8k16) ----------------
// CTA tile 64x64, K-block 64, 2-stage cp.async pipeline, 128 thr / 4 warps,
// 3 CTAs/SM. R5-proven mainloop: scalar LDS for B fragments (ldmatrix-B
// regressed twice) and pass-inner MMA order hh/hl/lh per accumulator
// (pass-outer neutral, QKV 128-tile regressed). BM=64 everywhere.
// EPI: 0=f32*alpha, 1=split bf16, 2=f32 residual +=, 3=classifier scatter,
//      4=residual += AND split-store, 5=fused GEGLU split-store (interleaved a/g cols)
template <int BM, int BN, int EPI>
__global__ __launch_bounds__((BM == 128 ? 256 : 128), (BM == 128 ? 1 : 3)) void hgemm(
    const bf16* __restrict__ Ah, const bf16* __restrict__ Al, long long lda, long long aS1, long long aS2,
    const bf16* __restrict__ Bh, const bf16* __restrict__ Bl, long long ldb, long long bS1, long long bS2,
    int K, int zdiv, float alpha,
    float* __restrict__ Cf, bf16* __restrict__ Ch, bf16* __restrict__ Cl,
    long long ldc, long long cS1, long long cS2, const float* __restrict__ bias) {
    extern __shared__ char sm[];
    constexpr int NT = (BM == 128 ? 256 : 128);
    constexpr int WN_CNT = NT / 64;            // 4 or 2
    constexpr int WN = BN / WN_CNT;            // warp n extent (32 both)
    constexpr int MI = BM / 32;                // m16 tiles per warp (4 or 2)
    constexpr int NREG = WN / 8;               // n8 tiles per warp (4)
    constexpr int RPI = NT / 8;                // rows loaded per iter (32 or 16)
    constexpr int AT = BM * 128;               // A tile bytes
    constexpr int BT = BN * 128;               // B tile bytes
    constexpr int STG = 2 * AT + 2 * BT;

    const int tid = threadIdx.x, lane = tid & 31, wid = tid >> 5;
    const int wm = wid & 1, wn = wid >> 1;
    const int zq = blockIdx.z / zdiv, zr = blockIdx.z - zq * zdiv;
    const int m0 = blockIdx.y * BM, n0 = blockIdx.x * BN;
    const bf16* Ahp = Ah + zq * aS1 + zr * aS2 + (size_t)m0 * lda;
    const bf16* Alp = Al + zq * aS1 + zr * aS2 + (size_t)m0 * lda;
    const bf16* Bhp = Bh + zq * bS1 + zr * bS2 + (size_t)n0 * ldb;
    const bf16* Blp = Bl + zq * bS1 + zr * bS2 + (size_t)n0 * ldb;
    const uint32_t sbase = smem_u32(sm);
    const int KB = K >> 6;

    float acc[MI][NREG][4];
#pragma unroll
    for (int a = 0; a < MI; a++)
#pragma unroll
        for (int b = 0; b < NREG; b++)
#pragma unroll
            for (int c = 0; c < 4; c++) acc[a][b][c] = 0.f;

    const int lr = tid >> 3, lc = tid & 7;

#define LOAD_STAGE(st, kb) do { \
    uint32_t bse = sbase + (st) * STG; \
    long long ko = (long long)(kb) * 64; \
    _Pragma("unroll") \
    for (int i = 0; i < BM / RPI; i++) { \
        int r = lr + i * RPI; \
        uint32_t so = SWZ(r * 128 + lc * 16); \
        CPASYNC(bse + so,      Ahp + (size_t)r * lda + ko + lc * 8); \
        CPASYNC(bse + AT + so, Alp + (size_t)r * lda + ko + lc * 8); \
    } \
    _Pragma("unroll") \
    for (int i = 0; i < BN / RPI; i++) { \
        int r = lr + i * RPI; \
        uint32_t so = SWZ(r * 128 + lc * 16); \
        CPASYNC(bse + 2 * AT + so,      Bhp + (size_t)r * ldb + ko + lc * 8); \
        CPASYNC(bse + 2 * AT + BT + so, Blp + (size_t)r * ldb + ko + lc * 8); \
    } \
    CPCOMMIT(); \
} while (0)

    LOAD_STAGE(0, 0);
    if (KB > 1) LOAD_STAGE(1, 1);

    const int g = lane >> 2, t4 = lane & 3;
    const int arow = wm * (BM / 2) + (lane & 15);
    const int acolb = (lane >> 4) * 16;

    for (int kb = 0; kb < KB; kb++) {
        if (kb + 2 <= KB) CPWAIT1(); else CPWAIT0();
        __syncthreads();
        uint32_t sAh = sbase + (kb & 1) * STG;
        uint32_t sAl = sAh + AT, sBh = sAh + 2 * AT, sBl = sBh + BT;
#pragma unroll
        for (int ks = 0; ks < 4; ks++) {
            uint32_t aH[MI][4], aL[MI][4], bH[NREG][2], bL[NREG][2];
#pragma unroll
            for (int mi = 0; mi < MI; mi++) {
                uint32_t off = SWZ((arow + mi * 16) * 128 + ks * 32 + acolb);
                ldsm4(aH[mi], sAh + off);
                ldsm4(aL[mi], sAl + off);
            }
#pragma unroll
            for (int ni = 0; ni < NREG; ni++) {
                int row = wn * WN + ni * 8 + g;
                uint32_t o0 = SWZ(row * 128 + ks * 32 + t4 * 4);
                uint32_t o1 = SWZ(row * 128 + ks * 32 + t4 * 4 + 16);
                bH[ni][0] = lds32(sBh + o0); bH[ni][1] = lds32(sBh + o1);
                bL[ni][0] = lds32(sBl + o0); bL[ni][1] = lds32(sBl + o1);
            }
#pragma unroll
            for (int mi = 0; mi < MI; mi++)
#pragma unroll
                for (int ni = 0; ni < NREG; ni++) {
                    mma_bf16(acc[mi][ni], aH[mi], bH[ni]);
                    mma_bf16(acc[mi][ni], aH[mi], bL[ni]);
                    mma_bf16(acc[mi][ni], aL[mi], bH[ni]);
                }
        }
        __syncthreads();
        if (kb + 2 < KB) LOAD_STAGE(kb & 1, kb + 2);
    }
#undef LOAD_STAGE

    // epilogue
    const long long coff = zq * cS1 + zr * cS2;
#pragma unroll
    for (int mi = 0; mi < MI; mi++) {
        int r0 = m0 + wm * (BM / 2) + mi * 16 + g;
        int r1 = r0 + 8;
#pragma unroll
        for (int ni = 0; ni < NREG; ni++) {
            int col = n0 + wn * WN + ni * 8 + t4 * 2;
            float v0 = acc[mi][ni][0], v1 = acc[mi][ni][1];
            float v2 = acc[mi][ni][2], v3 = acc[mi][ni][3];
            if (EPI == 0) {
                float2 p0 = {v0 * alpha, v1 * alpha}, p1 = {v2 * alpha, v3 * alpha};
                *(float2*)(Cf + coff + (size_t)r0 * ldc + col) = p0;
                *(float2*)(Cf + coff + (size_t)r1 * ldc + col) = p1;
            } else if (EPI == 1) {
                size_t i0 = coff + (size_t)r0 * ldc + col;
                size_t i1 = coff + (size_t)r1 * ldc + col;
                bf16 h0 = __float2bfloat16(v0), h1 = __float2bfloat16(v1);
                bf16 h2 = __float2bfloat16(v2), h3 = __float2bfloat16(v3);
                __nv_bfloat162 hh0; hh0.x = h0; hh0.y = h1;
                __nv_bfloat162 hh1; hh1.x = h2; hh1.y = h3;
                *(__nv_bfloat162*)(Ch + i0) = hh0;
                *(__nv_bfloat162*)(Ch + i1) = hh1;
                __nv_bfloat162 ll0, ll1;
                ll0.x = __float2bfloat16(v0 - __bfloat162float(h0));
                ll0.y = __float2bfloat16(v1 - __bfloat162float(h1));
                ll1.x = __float2bfloat16(v2 - __bfloat162float(h2));
                ll1.y = __float2bfloat16(v3 - __bfloat162float(h3));
                *(__nv_bfloat162*)(Cl + i0) = ll0;
                *(__nv_bfloat162*)(Cl + i1) = ll1;
            } else if (EPI == 2) {
                float* p0 = Cf + coff + (size_t)r0 * ldc + col;
                float* p1 = Cf + coff + (size_t)r1 * ldc + col;
                float2 c0 = *(float2*)p0, c1 = *(float2*)p1;
                c0.x += v0; c0.y += v1; c1.x += v2; c1.y += v3;
                *(float2*)p0 = c0; *(float2*)p1 = c1;
            } else if (EPI == 4) {
                size_t i0 = coff + (size_t)r0 * ldc + col;
                size_t i1 = coff + (size_t)r1 * ldc + col;
                float2 c0 = *(float2*)(Cf + i0), c1 = *(float2*)(Cf + i1);
                c0.x += v0; c0.y += v1; c1.x += v2; c1.y += v3;
                *(float2*)(Cf + i0) = c0; *(float2*)(Cf + i1) = c1;
                bf16 h0 = __float2bfloat16(c0.x), h1 = __float2bfloat16(c0.y);
                bf16 h2 = __float2bfloat16(c1.x), h3 = __float2bfloat16(c1.y);
                __nv_bfloat162 hh0; hh0.x = h0; hh0.y = h1;
                __nv_bfloat162 hh1; hh1.x = h2; hh1.y = h3;
                *(__nv_bfloat162*)(Ch + i0) = hh0;
                *(__nv_bfloat162*)(Ch + i1) = hh1;
                __nv_bfloat162 ll0, ll1;
                ll0.x = __float2bfloat16(c0.x - __bfloat162float(h0));
                ll0.y = __float2bfloat16(c0.y - __bfloat162float(h1));
                ll1.x = __float2bfloat16(c1.x - __bfloat162float(h2));
                ll1.y = __float2bfloat16(c1.y - __bfloat162float(h3));
                *(__nv_bfloat162*)(Cl + i0) = ll0;
                *(__nv_bfloat162*)(Cl + i1) = ll1;
            } else if (EPI == 5) {
                // fused GEGLU: col even = a_j, col odd = g_j, j = col/2
                int j = col >> 1;
                float t0 = tanhf(0.7978845608028654f * (v1 + 0.044715f * v1 * v1 * v1));
                float w0 = v0 * (0.5f * v1 * (1.0f + t0));
                float t1 = tanhf(0.7978845608028654f * (v3 + 0.044715f * v3 * v3 * v3));
                float w1v = v2 * (0.5f * v3 * (1.0f + t1));
                spst(w0, Ch, Cl, (size_t)r0 * ldc + j);
                spst(w1v, Ch, Cl, (size_t)r1 * ldc + j);
            } else {
                int b0 = r0 >> 9, s0 = r0 & 511, b1 = r1 >> 9, s1 = r1 & 511;
#pragma unroll
                for (int e = 0; e < 2; e++) {
                    int cc = col + e;
                    int vv = cc / 10, pp = cc - vv * 10;
                    float bv = bias[cc];
                    Cf[(size_t)b0 * OUT_PER_B + (size_t)vv * 5120 + s0 * 10 + pp] = (e ? v1 : v0) + bv;
                    Cf[(size_t)b1 * OUT_PER_B + (size_t)vv * 5120 + s1 * 10 + pp] = (e ? v3 : v2) + bv;
                }
            }
        }
    }
}

// ---------------- host ----------------
extern "C" void kernel_launch(void* const* d_in, const int* in_sizes, int n_in,
                              void* d_out, int out_size) {
    const float* latents  = (const float*)d_in[0];
    const float* emb_w    = (const float*)d_in[1];
    const float* emb_b    = (const float*)d_in[2];
    const float* norm_w   = (const float*)d_in[3];
    const float* wq       = (const float*)d_in[4];
    const float* wk       = (const float*)d_in[5];
    const float* wv       = (const float*)d_in[6];
    const float* wo       = (const float*)d_in[7];
    const float* w1       = (const float*)d_in[8];
    const float* w2       = (const float*)d_in[9];
    const float* rel_bias = (const float*)d_in[10];
    const float* now      = (const float*)d_in[11];
    const float* cls_w    = (const float*)d_in[12];
    const float* cls_b    = (const float*)d_in[13];
    float* out = (float*)d_out;

    bf16* bfp = nullptr; float* fp = nullptr;
    cudaGetSymbolAddress((void**)&bfp, g_bf);
    cudaGetSymbolAddress((void**)&fp, g_f);

    const int SM64  = 2 * (2 * 64 * 128 + 2 * 64 * 128);    // 65536
    const int SM64_1STG = SM64 / 2;                          // 32768 (KB=1 kernels)
    cudaFuncSetAttribute(hgemm<64,64,0>, cudaFuncAttributeMaxDynamicSharedMemorySize, SM64);
    cudaFuncSetAttribute(hgemm<64,64,1>, cudaFuncAttributeMaxDynamicSharedMemorySize, SM64);
    cudaFuncSetAttribute(hgemm<64,64,2>, cudaFuncAttributeMaxDynamicSharedMemorySize, SM64);
    cudaFuncSetAttribute(hgemm<64,64,3>, cudaFuncAttributeMaxDynamicSharedMemorySize, SM64);
    cudaFuncSetAttribute(hgemm<64,64,4>, cudaFuncAttributeMaxDynamicSharedMemorySize, SM64);
    cudaFuncSetAttribute(hgemm<64,64,5>, cudaFuncAttributeMaxDynamicSharedMemorySize, SM64);

    float* x  = fp + OF_X;
    float* sc = fp + OF_S;

    // weight prep: vectorized transpose [K][N] -> [N][K] + split hi/lo
    trans_split<<<dim3(40, 20, 16), 256>>>(wq, 1638400, 1280, 1280, bfp + O_QKVT_H,           bfp + O_QKVT_L,           4915200, 0);
    trans_split<<<dim3(40, 20, 16), 256>>>(wk, 1638400, 1280, 1280, bfp + O_QKVT_H + 1638400, bfp + O_QKVT_L + 1638400, 4915200, 0);
    trans_split<<<dim3(40, 20, 16), 256>>>(wv, 1638400, 1280, 1280, bfp + O_QKVT_H + 3276800, bfp + O_QKVT_L + 3276800, 4915200, 0);
    trans_split<<<dim3(40, 20, 16), 256>>>(wo, 1638400, 1280, 1280, bfp + O_WOT_H, bfp + O_WOT_L, 1638400, 0);
    trans_split<<<dim3(160, 20, 16), 256>>>(w1, 6553600, 1280, 5120, bfp + O_W1T_H, bfp + O_W1T_L, 6553600, DI_);
    trans_split<<<dim3(40, 40, 16), 256>>>(w2, 3276800, 2560, 1280, bfp + O_W2T_H, bfp + O_W2T_L, 3276800, 0);
    split_kernel<<<12800, 256>>>(cls_w, bfp + O_CLST_H, bfp + O_CLST_L);

    embed_kernel<<<dim3(5, 1024), 256>>>(latents, emb_w, emb_b, x);

    for (int l = 0; l < L_; l++) {
        rmsnorm_kernel<<<T_, 256>>>(x, norm_w + (size_t)l * D_, bfp + O_H_H, bfp + O_H_L);
        // QKV: [1024,1280] @ [3840,1280]^T -> split qkv, 64x64 tiles (960 CTAs)
        hgemm<64,64,1><<<dim3(60, 16, 1), 128, SM64>>>(
            bfp + O_H_H, bfp + O_H_L, 1280, 0, 0,
            bfp + O_QKVT_H + (size_t)l * 4915200, bfp + O_QKVT_L + (size_t)l * 4915200, 1280, 0, 0,
            1280, 1, 1.f, nullptr, bfp + O_QKV_H, bfp + O_QKV_L, 3840, 0, 0, nullptr);
        vtrans_kernel<<<dim3(16, 40), 256>>>(bfp + O_QKV_H, bfp + O_QKV_L, bfp + O_VT_H, bfp + O_VT_L);
        // scores: per bh q[512,64] @ k[512,64]^T * 0.125 -> f32; 64x64, 32KB smem
        hgemm<64,64,0><<<dim3(8, 8, 40), 128, SM64_1STG>>>(
            bfp + O_QKV_H, bfp + O_QKV_L, 3840, 1966080, 64,
            bfp + O_QKV_H + 1280, bfp + O_QKV_L + 1280, 3840, 1966080, 64,
            64, 20, 0.125f, sc, nullptr, nullptr, 512, 5242880, 262144, nullptr);
        softmax_kernel<<<dim3(512, 40), 256>>>(sc, rel_bias, bfp + O_ATT_H, bfp + O_ATT_L, l == 0 ? 1 : 0);
        // AV: att[512,512] @ vt[64,512]^T -> o split, 64x64 tiles
        hgemm<64,64,1><<<dim3(1, 8, 40), 128, SM64>>>(
            bfp + O_ATT_H, bfp + O_ATT_L, 512, 5242880, 262144,
            bfp + O_VT_H, bfp + O_VT_L, 512, 655360, 32768,
            512, 20, 1.f, nullptr, bfp + O_O_H, bfp + O_O_L, 1280, 655360, 64, nullptr);
        // x += o @ woT, fused split-store -> xs, 64x64 tiles
        hgemm<64,64,4><<<dim3(20, 16, 1), 128, SM64>>>(
            bfp + O_O_H, bfp + O_O_L, 1280, 0, 0,
            bfp + O_WOT_H + (size_t)l * 1638400, bfp + O_WOT_L + (size_t)l * 1638400, 1280, 0, 0,
            1280, 1, 1.f, x, bfp + O_XS_H, bfp + O_XS_L, 1280, 0, 0, nullptr);
        // gate = geglu(x @ w1T) fused in epilogue (interleaved W1T), 64x64 tiles
        hgemm<64,64,5><<<dim3(80, 16, 1), 128, SM64>>>(
            bfp + O_XS_H, bfp + O_XS_L, 1280, 0, 0,
            bfp + O_W1T_H + (size_t)l * 6553600, bfp + O_W1T_L + (size_t)l * 6553600, 1280, 0, 0,
            1280, 1, 1.f, nullptr, bfp + O_G_H, bfp + O_G_L, 2560, 0, 0, nullptr);
        // x += g @ w2T, 64x64 tiles
        hgemm<64,64,2><<<dim3(20, 16, 1), 128, SM64>>>(
            bfp + O_G_H, bfp + O_G_L, 2560, 0, 0,
            bfp + O_W2T_H + (size_t)l * 3276800, bfp + O_W2T_L + (size_t)l * 3276800, 2560, 0, 0,
            2560, 1, 1.f, x, nullptr, nullptr, 1280, 0, 0, nullptr);
    }

    rmsnorm_kernel<<<T_, 256>>>(x, now, bfp + O_H_H, bfp + O_H_L);
    // classifier, 64x64 tiles
    hgemm<64,64,3><<<dim3(160, 16, 1), 128, SM64>>>(
        bfp + O_H_H, bfp + O_H_L, 1280, 0, 0,
        bfp + O_CLST_H, bfp + O_CLST_L, 1280, 0, 0,
        1280, 1, 1.f, out, nullptr, nullptr, 0, 0, 0, cls_b);
}

// round 16
// speedup vs baseline: 1.0397x; 1.0107x over previous
#include <cuda_runtime.h>
#include <cuda_bf16.h>
#include <math.h>
#include <stdint.h>

typedef __nv_bfloat16 bf16;

#define B_   2
#define S_   512
#define T_   1024
#define D_   1280
#define H_   20
#define L_   16
#define DI_  2560
#define W1O_ 5120
#define OUT_PER_B 5242880

// ---------------- PTX helpers (baseline, non-'a' features only) ----------------
__device__ __forceinline__ uint32_t smem_u32(const void* p) {
    uint32_t a;
    asm("{ .reg .u64 t; cvta.to.shared.u64 t, %1; cvt.u32.u64 %0, t; }" : "=r"(a) : "l"(p));
    return a;
}
#define SWZ(o) ((o) ^ (((o) >> 3) & 0x70))

#define CPASYNC(dst, src) \
    asm volatile("cp.async.cg.shared.global [%0], [%1], 16;" :: "r"(dst), "l"(src))
#define CPCOMMIT() asm volatile("cp.async.commit_group;" ::: "memory")
#define CPWAIT1()  asm volatile("cp.async.wait_group 1;" ::: "memory")
#define CPWAIT0()  asm volatile("cp.async.wait_group 0;" ::: "memory")

__device__ __forceinline__ void ldsm4(uint32_t* r, uint32_t addr) {
    asm volatile("ldmatrix.sync.aligned.m8n8.x4.shared.b16 {%0,%1,%2,%3}, [%4];"
        : "=r"(r[0]), "=r"(r[1]), "=r"(r[2]), "=r"(r[3]) : "r"(addr));
}
__device__ __forceinline__ uint32_t lds32(uint32_t addr) {
    uint32_t v;
    asm volatile("ld.shared.b32 %0, [%1];" : "=r"(v) : "r"(addr));
    return v;
}
__device__ __forceinline__ void mma_bf16(float* d, const uint32_t* a, const uint32_t* b) {
    asm volatile(
        "mma.sync.aligned.m16n8k16.row.col.f32.bf16.bf16.f32 "
        "{%0,%1,%2,%3}, {%4,%5,%6,%7}, {%8,%9}, {%0,%1,%2,%3};"
        : "+f"(d[0]), "+f"(d[1]), "+f"(d[2]), "+f"(d[3])
        : "r"(a[0]), "r"(a[1]), "r"(a[2]), "r"(a[3]), "r"(b[0]), "r"(b[1]));
}

// ---------------- scratch (bf16 arena) ----------------
#define O_QKVT_H 0ll
#define O_QKVT_L 78643200ll
#define O_WOT_H  157286400ll
#define O_WOT_L  183500800ll
#define O_W1T_H  209715200ll
#define O_W1T_L  314572800ll
#define O_W2T_H  419430400ll
#define O_W2T_L  471859200ll
#define O_CLST_H 524288000ll
#define O_CLST_L 537395200ll
#define O_H_H    550502400ll
#define O_H_L    551813120ll
#define O_QKV_H  553123840ll
#define O_QKV_L  557056000ll
#define O_VT_H   560988160ll
#define O_VT_L   562331648ll
#define O_ATT_H  563675136ll
#define O_ATT_L  574160896ll
#define O_O_H    584646656ll
#define O_O_L    585957376ll
#define O_XS_H   587268096ll
#define O_XS_L   588578816ll
#define O_G_H    589889536ll
#define O_G_L    592510976ll
__device__ bf16 g_bf[595132416ll];
#define OF_X 0
#define OF_S 6553600
__device__ float g_f[17039360];

// ---------------- small kernels ----------------
__global__ void embed_kernel(const float* __restrict__ lat, const float* __restrict__ ew,
                             const float* __restrict__ eb, float* __restrict__ x) {
    int t = blockIdx.y, d = blockIdx.x * 256 + threadIdx.x;
    __shared__ float l[112];
    int b = t >> 9, n = t & 511;
    if (threadIdx.x < 112) l[threadIdx.x] = lat[(size_t)b * 57344 + threadIdx.x * 512 + n];
    __syncthreads();
    float s = eb[d];
    const float* w = ew + (size_t)d * 112;
#pragma unroll 8
    for (int c = 0; c < 112; c++) s += l[c] * w[c];
    x[(size_t)t * D_ + d] = s;
}

__device__ __forceinline__ void spst(float v, bf16* hi, bf16* lo, size_t i) {
    bf16 h = __float2bfloat16(v);
    hi[i] = h;
    lo[i] = __float2bfloat16(v - __bfloat162float(h));
}

__global__ __launch_bounds__(256) void rmsnorm_kernel(const float* __restrict__ x,
                                                      const float* __restrict__ w,
                                                      bf16* __restrict__ oh, bf16* __restrict__ ol) {
    int t = blockIdx.x;
    const float* xr = x + (size_t)t * D_;
    float ss = 0.f;
    for (int i = threadIdx.x; i < D_; i += 256) { float v = xr[i]; ss += v * v; }
    __shared__ float red[8];
    float v = ss;
#pragma unroll
    for (int o = 16; o; o >>= 1) v += __shfl_down_sync(~0u, v, o);
    if ((threadIdx.x & 31) == 0) red[threadIdx.x >> 5] = v;
    __syncthreads();
    if (threadIdx.x == 0) { float r = 0.f; for (int i = 0; i < 8; i++) r += red[i]; red[0] = r; }
    __syncthreads();
    float inv = rsqrtf(red[0] / (float)D_ + 1e-5f);
    size_t b = (size_t)t * D_;
    for (int i = threadIdx.x; i < D_; i += 256) spst(w[i] * (xr[i] * inv), oh, ol, b + i);
}

__device__ __forceinline__ float relbias(const float* __restrict__ rb, int i, int j, int h) {
    int n = i - j, ret = (n < 0) ? 16 : 0, an = (n < 0) ? -n : n, val;
    if (an < 8) val = an;
    else { val = 8 + (int)(logf((float)an * 0.125f) * (8.0f / logf(16.0f))); if (val > 15) val = 15; }
    return rb[(ret + val) * H_ + h];
}

__global__ __launch_bounds__(256) void softmax_kernel(const float* __restrict__ sc,
                                                      const float* __restrict__ rb,
                                                      bf16* __restrict__ ah, bf16* __restrict__ al,
                                                      int add_bias) {
    int i = blockIdx.x, bh = blockIdx.y, h = bh % H_, tid = threadIdx.x;
    const float* p = sc + ((size_t)bh * S_ + i) * S_;
    float v0 = p[tid], v1 = p[tid + 256];
    if (add_bias) { v0 += relbias(rb, i, tid, h); v1 += relbias(rb, i, tid + 256, h); }
    float m = fmaxf(v0, v1);
    __shared__ float rm[8], rs[8];
#pragma unroll
    for (int o = 16; o; o >>= 1) m = fmaxf(m, __shfl_down_sync(~0u, m, o));
    if ((tid & 31) == 0) rm[tid >> 5] = m;
    __syncthreads();
    if (tid == 0) { float mm = rm[0]; for (int k = 1; k < 8; k++) mm = fmaxf(mm, rm[k]); rm[0] = mm; }
    __syncthreads();
    float bm = rm[0], e0 = expf(v0 - bm), e1 = expf(v1 - bm), s = e0 + e1;
#pragma unroll
    for (int o = 16; o; o >>= 1) s += __shfl_down_sync(~0u, s, o);
    if ((tid & 31) == 0) rs[tid >> 5] = s;
    __syncthreads();
    if (tid == 0) { float t = 0.f; for (int k = 0; k < 8; k++) t += rs[k]; rs[0] = t; }
    __syncthreads();
    float inv = 1.0f / rs[0];
    size_t ob = ((size_t)bh * S_ + i) * S_;
    spst(e0 * inv, ah, al, ob + tid);
    spst(e1 * inv, ah, al, ob + tid + 256);
}

// vectorized fp32 -> split bf16 (uint2 stores)
__global__ void split_kernel(const float* __restrict__ s, bf16* __restrict__ hi, bf16* __restrict__ lo) {
    int i = (blockIdx.x * 256 + threadIdx.x) << 2;
    float4 v = *(const float4*)(s + i);
    bf16 h4[4], l4[4];
    float vv[4] = {v.x, v.y, v.z, v.w};
#pragma unroll
    for (int j = 0; j < 4; j++) {
        bf16 h = __float2bfloat16(vv[j]);
        h4[j] = h;
        l4[j] = __float2bfloat16(vv[j] - __bfloat162float(h));
    }
    *(uint2*)(hi + i) = *(uint2*)h4;
    *(uint2*)(lo + i) = *(uint2*)l4;
}

// transpose+split (vectorized): src fp32 [K][N] (z-batched) -> dst bf16 [N][K] hi/lo.
// tile 64k x 32n; each thread stores 8 contiguous bf16 (uint4) per array.
// di>0: interleave row perm for fused GEGLU (a_j -> 2j, g_j -> 2j+1).
__global__ __launch_bounds__(256) void trans_split(const float* __restrict__ src, long long sZ,
                                                   int K, int N,
                                                   bf16* __restrict__ dh, bf16* __restrict__ dl,
                                                   long long dZ, int di) {
    __shared__ float t[64][33];
    int n0 = blockIdx.x * 32, k0 = blockIdx.y * 64;
    const float* s = src + (size_t)blockIdx.z * sZ;
    int c = threadIdx.x & 31, r0 = threadIdx.x >> 5;
#pragma unroll
    for (int i = 0; i < 8; i++)
        t[r0 + i * 8][c] = s[(size_t)(k0 + r0 + i * 8) * N + n0 + c];
    __syncthreads();
    int n_i = threadIdx.x >> 3, kg = threadIdx.x & 7;
    int n = n0 + n_i;
    int nr = di ? ((n < di) ? 2 * n : 2 * (n - di) + 1) : n;
    size_t base = (size_t)blockIdx.z * dZ + (size_t)nr * K + k0 + kg * 8;
    bf16 h8[8], l8[8];
#pragma unroll
    for (int j = 0; j < 8; j++) {
        float v = t[kg * 8 + j][n_i];
        bf16 h = __float2bfloat16(v);
        h8[j] = h;
        l8[j] = __float2bfloat16(v - __bfloat162float(h));
    }
    *(uint4*)(dh + base) = *(uint4*)h8;
    *(uint4*)(dl + base) = *(uint4*)l8;
}

// ---------------- split-bf16 HMMA GEMM (mma.sync m16n8k16) ----------------
// CTA tile 64x64, K-block 64, 2-stage cp.async pipeline, 128 thr / 4 warps,
// 3 CTAs/SM. R5-proven mainloop: scalar LDS for B fragments (ldmatrix-B
// regressed twice) and pass-inner MMA order hh/hl/lh per accumulator.
// EPI: 0=f32*alpha, 1=split bf16, 2=f32 residual +=, 3=classifier scatter,
//      4=residual += AND split-store, 5=fused GEGLU split-store,
//      6=QKV: split bf16 for q/k cols, direct transposed vt store for v cols
template <int BM, int BN, int EPI>
__global__ __launch_bounds__((BM == 128 ? 256 : 128), (BM == 128 ? 1 : 3)) void hgemm(
    const bf16* __restrict__ Ah, const bf16* __restrict__ Al, long long lda, long long aS1, long long aS2,
    const bf16* __restrict__ Bh, const bf16* __restrict__ Bl, long long ldb, long long bS1, long long bS2,
    int K, int zdiv, float alpha,
    float* __restrict__ Cf, bf16* __restrict__ Ch, bf16* __restrict__ Cl,
    long long ldc, long long cS1, long long cS2, const float* __restrict__ bias,
    bf16* __restrict__ Vh, bf16* __restrict__ Vl) {
    extern __shared__ char sm[];
    constexpr int NT = (BM == 128 ? 256 : 128);
    constexpr int WN_CNT = NT / 64;            // 4 or 2
    constexpr int WN = BN / WN_CNT;            // warp n extent (32 both)
    constexpr int MI = BM / 32;                // m16 tiles per warp (4 or 2)
    constexpr int NREG = WN / 8;               // n8 tiles per warp (4)
    constexpr int RPI = NT / 8;                // rows loaded per iter (32 or 16)
    constexpr int AT = BM * 128;               // A tile bytes
    constexpr int BT = BN * 128;               // B tile bytes
    constexpr int STG = 2 * AT + 2 * BT;

    const int tid = threadIdx.x, lane = tid & 31, wid = tid >> 5;
    const int wm = wid & 1, wn = wid >> 1;
    const int zq = blockIdx.z / zdiv, zr = blockIdx.z - zq * zdiv;
    const int m0 = blockIdx.y * BM, n0 = blockIdx.x * BN;
    const bf16* Ahp = Ah + zq * aS1 + zr * aS2 + (size_t)m0 * lda;
    const bf16* Alp = Al + zq * aS1 + zr * aS2 + (size_t)m0 * lda;
    const bf16* Bhp = Bh + zq * bS1 + zr * bS2 + (size_t)n0 * ldb;
    const bf16* Blp = Bl + zq * bS1 + zr * bS2 + (size_t)n0 * ldb;
    const uint32_t sbase = smem_u32(sm);
    const int KB = K >> 6;

    float acc[MI][NREG][4];
#pragma unroll
    for (int a = 0; a < MI; a++)
#pragma unroll
        for (int b = 0; b < NREG; b++)
#pragma unroll
            for (int c = 0; c < 4; c++) acc[a][b][c] = 0.f;

    const int lr = tid >> 3, lc = tid & 7;

#define LOAD_STAGE(st, kb) do { \
    uint32_t bse = sbase + (st) * STG; \
    long long ko = (long long)(kb) * 64; \
    _Pragma("unroll") \
    for (int i = 0; i < BM / RPI; i++) { \
        int r = lr + i * RPI; \
        uint32_t so = SWZ(r * 128 + lc * 16); \
        CPASYNC(bse + so,      Ahp + (size_t)r * lda + ko + lc * 8); \
        CPASYNC(bse + AT + so, Alp + (size_t)r * lda + ko + lc * 8); \
    } \
    _Pragma("unroll") \
    for (int i = 0; i < BN / RPI; i++) { \
        int r = lr + i * RPI; \
        uint32_t so = SWZ(r * 128 + lc * 16); \
        CPASYNC(bse + 2 * AT + so,      Bhp + (size_t)r * ldb + ko + lc * 8); \
        CPASYNC(bse + 2 * AT + BT + so, Blp + (size_t)r * ldb + ko + lc * 8); \
    } \
    CPCOMMIT(); \
} while (0)

    LOAD_STAGE(0, 0);
    if (KB > 1) LOAD_STAGE(1, 1);

    const int g = lane >> 2, t4 = lane & 3;
    const int arow = wm * (BM / 2) + (lane & 15);
    const int acolb = (lane >> 4) * 16;

    for (int kb = 0; kb < KB; kb++) {
        if (kb + 2 <= KB) CPWAIT1(); else CPWAIT0();
        __syncthreads();
        uint32_t sAh = sbase + (kb & 1) * STG;
        uint32_t sAl = sAh + AT, sBh = sAh + 2 * AT, sBl = sBh + BT;
#pragma unroll
        for (int ks = 0; ks < 4; ks++) {
            uint32_t aH[MI][4], aL[MI][4], bH[NREG][2], bL[NREG][2];
#pragma unroll
            for (int mi = 0; mi < MI; mi++) {
                uint32_t off = SWZ((arow + mi * 16) * 128 + ks * 32 + acolb);
                ldsm4(aH[mi], sAh + off);
                ldsm4(aL[mi], sAl + off);
            }
#pragma unroll
            for (int ni = 0; ni < NREG; ni++) {
                int row = wn * WN + ni * 8 + g;
                uint32_t o0 = SWZ(row * 128 + ks * 32 + t4 * 4);
                uint32_t o1 = SWZ(row * 128 + ks * 32 + t4 * 4 + 16);
                bH[ni][0] = lds32(sBh + o0); bH[ni][1] = lds32(sBh + o1);
                bL[ni][0] = lds32(sBl + o0); bL[ni][1] = lds32(sBl + o1);
            }
#pragma unroll
            for (int mi = 0; mi < MI; mi++)
#pragma unroll
                for (int ni = 0; ni < NREG; ni++) {
                    mma_bf16(acc[mi][ni], aH[mi], bH[ni]);
                    mma_bf16(acc[mi][ni], aH[mi], bL[ni]);
                    mma_bf16(acc[mi][ni], aL[mi], bH[ni]);
                }
        }
        __syncthreads();
        if (kb + 2 < KB) LOAD_STAGE(kb & 1, kb + 2);
    }
#undef LOAD_STAGE

    // epilogue
    const long long coff = zq * cS1 + zr * cS2;
#pragma unroll
    for (int mi = 0; mi < MI; mi++) {
        int r0 = m0 + wm * (BM / 2) + mi * 16 + g;
        int r1 = r0 + 8;
#pragma unroll
        for (int ni = 0; ni < NREG; ni++) {
            int col = n0 + wn * WN + ni * 8 + t4 * 2;
            float v0 = acc[mi][ni][0], v1 = acc[mi][ni][1];
            float v2 = acc[mi][ni][2], v3 = acc[mi][ni][3];
            if (EPI == 0) {
                float2 p0 = {v0 * alpha, v1 * alpha}, p1 = {v2 * alpha, v3 * alpha};
                *(float2*)(Cf + coff + (size_t)r0 * ldc + col) = p0;
                *(float2*)(Cf + coff + (size_t)r1 * ldc + col) = p1;
            } else if (EPI == 1 || EPI == 6) {
                if (EPI == 6 && col >= 2560) {
                    // v columns: write directly into vt[bh][dk][t] (split),
                    // bitwise-identical values to the old vtrans copy path
                    int hh = (col - 2560) >> 6, dk = (col - 2560) & 63;
                    int b0 = r0 >> 9, s0 = r0 & 511;
                    int b1 = r1 >> 9, s1 = r1 & 511;
                    size_t i0 = ((size_t)(b0 * H_ + hh) * 64 + dk) * 512 + s0;
                    size_t i1 = ((size_t)(b1 * H_ + hh) * 64 + dk) * 512 + s1;
                    spst(v0, Vh, Vl, i0);
                    spst(v1, Vh, Vl, i0 + 512);
                    spst(v2, Vh, Vl, i1);
                    spst(v3, Vh, Vl, i1 + 512);
                } else {
                    size_t i0 = coff + (size_t)r0 * ldc + col;
                    size_t i1 = coff + (size_t)r1 * ldc + col;
                    bf16 h0 = __float2bfloat16(v0), h1 = __float2bfloat16(v1);
                    bf16 h2 = __float2bfloat16(v2), h3 = __float2bfloat16(v3);
                    __nv_bfloat162 hh0; hh0.x = h0; hh0.y = h1;
                    __nv_bfloat162 hh1; hh1.x = h2; hh1.y = h3;
                    *(__nv_bfloat162*)(Ch + i0) = hh0;
                    *(__nv_bfloat162*)(Ch + i1) = hh1;
                    __nv_bfloat162 ll0, ll1;
                    ll0.x = __float2bfloat16(v0 - __bfloat162float(h0));
                    ll0.y = __float2bfloat16(v1 - __bfloat162float(h1));
                    ll1.x = __float2bfloat16(v2 - __bfloat162float(h2));
                    ll1.y = __float2bfloat16(v3 - __bfloat162float(h3));
                    *(__nv_bfloat162*)(Cl + i0) = ll0;
                    *(__nv_bfloat162*)(Cl + i1) = ll1;
                }
            } else if (EPI == 2) {
                float* p0 = Cf + coff + (size_t)r0 * ldc + col;
                float* p1 = Cf + coff + (size_t)r1 * ldc + col;
                float2 c0 = *(float2*)p0, c1 = *(float2*)p1;
                c0.x += v0; c0.y += v1; c1.x += v2; c1.y += v3;
                *(float2*)p0 = c0; *(float2*)p1 = c1;
            } else if (EPI == 4) {
                size_t i0 = coff + (size_t)r0 * ldc + col;
                size_t i1 = coff + (size_t)r1 * ldc + col;
                float2 c0 = *(float2*)(Cf + i0), c1 = *(float2*)(Cf + i1);
                c0.x += v0; c0.y += v1; c1.x += v2; c1.y += v3;
                *(float2*)(Cf + i0) = c0; *(float2*)(Cf + i1) = c1;
                bf16 h0 = __float2bfloat16(c0.x), h1 = __float2bfloat16(c0.y);
                bf16 h2 = __float2bfloat16(c1.x), h3 = __float2bfloat16(c1.y);
                __nv_bfloat162 hh0; hh0.x = h0; hh0.y = h1;
                __nv_bfloat162 hh1; hh1.x = h2; hh1.y = h3;
                *(__nv_bfloat162*)(Ch + i0) = hh0;
                *(__nv_bfloat162*)(Ch + i1) = hh1;
                __nv_bfloat162 ll0, ll1;
                ll0.x = __float2bfloat16(c0.x - __bfloat162float(h0));
                ll0.y = __float2bfloat16(c0.y - __bfloat162float(h1));
                ll1.x = __float2bfloat16(c1.x - __bfloat162float(h2));
                ll1.y = __float2bfloat16(c1.y - __bfloat162float(h3));
                *(__nv_bfloat162*)(Cl + i0) = ll0;
                *(__nv_bfloat162*)(Cl + i1) = ll1;
            } else if (EPI == 5) {
                // fused GEGLU: col even = a_j, col odd = g_j, j = col/2
                int j = col >> 1;
                float t0 = tanhf(0.7978845608028654f * (v1 + 0.044715f * v1 * v1 * v1));
                float w0 = v0 * (0.5f * v1 * (1.0f + t0));
                float t1 = tanhf(0.7978845608028654f * (v3 + 0.044715f * v3 * v3 * v3));
                float w1v = v2 * (0.5f * v3 * (1.0f + t1));
                spst(w0, Ch, Cl, (size_t)r0 * ldc + j);
                spst(w1v, Ch, Cl, (size_t)r1 * ldc + j);
            } else if (EPI == 3) {
                int b0 = r0 >> 9, s0 = r0 & 511, b1 = r1 >> 9, s1 = r1 & 511;
#pragma unroll
                for (int e = 0; e < 2; e++) {
                    int cc = col + e;
                    int vv = cc / 10, pp = cc - vv * 10;
                    float bv = bias[cc];
                    Cf[(size_t)b0 * OUT_PER_B + (size_t)vv * 5120 + s0 * 10 + pp] = (e ? v1 : v0) + bv;
                    Cf[(size_t)b1 * OUT_PER_B + (size_t)vv * 5120 + s1 * 10 + pp] = (e ? v3 : v2) + bv;
                }
            }
        }
    }
}

// ---------------- host ----------------
extern "C" void kernel_launch(void* const* d_in, const int* in_sizes, int n_in,
                              void* d_out, int out_size) {
    const float* latents  = (const float*)d_in[0];
    const float* emb_w    = (const float*)d_in[1];
    const float* emb_b    = (const float*)d_in[2];
    const float* norm_w   = (const float*)d_in[3];
    const float* wq       = (const float*)d_in[4];
    const float* wk       = (const float*)d_in[5];
    const float* wv       = (const float*)d_in[6];
    const float* wo       = (const float*)d_in[7];
    const float* w1       = (const float*)d_in[8];
    const float* w2       = (const float*)d_in[9];
    const float* rel_bias = (const float*)d_in[10];
    const float* now      = (const float*)d_in[11];
    const float* cls_w    = (const float*)d_in[12];
    const float* cls_b    = (const float*)d_in[13];
    float* out = (float*)d_out;

    bf16* bfp = nullptr; float* fp = nullptr;
    cudaGetSymbolAddress((void**)&bfp, g_bf);
    cudaGetSymbolAddress((void**)&fp, g_f);

    const int SM64  = 2 * (2 * 64 * 128 + 2 * 64 * 128);    // 65536
    const int SM64_1STG = SM64 / 2;                          // 32768 (KB=1 kernels)
    cudaFuncSetAttribute(hgemm<64,64,0>, cudaFuncAttributeMaxDynamicSharedMemorySize, SM64);
    cudaFuncSetAttribute(hgemm<64,64,1>, cudaFuncAttributeMaxDynamicSharedMemorySize, SM64);
    cudaFuncSetAttribute(hgemm<64,64,2>, cudaFuncAttributeMaxDynamicSharedMemorySize, SM64);
    cudaFuncSetAttribute(hgemm<64,64,3>, cudaFuncAttributeMaxDynamicSharedMemorySize, SM64);
    cudaFuncSetAttribute(hgemm<64,64,4>, cudaFuncAttributeMaxDynamicSharedMemorySize, SM64);
    cudaFuncSetAttribute(hgemm<64,64,5>, cudaFuncAttributeMaxDynamicSharedMemorySize, SM64);
    cudaFuncSetAttribute(hgemm<64,64,6>, cudaFuncAttributeMaxDynamicSharedMemorySize, SM64);

    float* x  = fp + OF_X;
    float* sc = fp + OF_S;

    // weight prep: vectorized transpose [K][N] -> [N][K] + split hi/lo
    trans_split<<<dim3(40, 20, 16), 256>>>(wq, 1638400, 1280, 1280, bfp + O_QKVT_H,           bfp + O_QKVT_L,           4915200, 0);
    trans_split<<<dim3(40, 20, 16), 256>>>(wk, 1638400, 1280, 1280, bfp + O_QKVT_H + 1638400, bfp + O_QKVT_L + 1638400, 4915200, 0);
    trans_split<<<dim3(40, 20, 16), 256>>>(wv, 1638400, 1280, 1280, bfp + O_QKVT_H + 3276800, bfp + O_QKVT_L + 3276800, 4915200, 0);
    trans_split<<<dim3(40, 20, 16), 256>>>(wo, 1638400, 1280, 1280, bfp + O_WOT_H, bfp + O_WOT_L, 1638400, 0);
    trans_split<<<dim3(160, 20, 16), 256>>>(w1, 6553600, 1280, 5120, bfp + O_W1T_H, bfp + O_W1T_L, 6553600, DI_);
    trans_split<<<dim3(40, 40, 16), 256>>>(w2, 3276800, 2560, 1280, bfp + O_W2T_H, bfp + O_W2T_L, 3276800, 0);
    split_kernel<<<12800, 256>>>(cls_w, bfp + O_CLST_H, bfp + O_CLST_L);

    embed_kernel<<<dim3(5, 1024), 256>>>(latents, emb_w, emb_b, x);

    for (int l = 0; l < L_; l++) {
        rmsnorm_kernel<<<T_, 256>>>(x, norm_w + (size_t)l * D_, bfp + O_H_H, bfp + O_H_L);
        // QKV: 64x64 tiles; q/k -> qkv buffer, v -> vt directly (fused vtrans)
        hgemm<64,64,6><<<dim3(60, 16, 1), 128, SM64>>>(
            bfp + O_H_H, bfp + O_H_L, 1280, 0, 0,
            bfp + O_QKVT_H + (size_t)l * 4915200, bfp + O_QKVT_L + (size_t)l * 4915200, 1280, 0, 0,
            1280, 1, 1.f, nullptr, bfp + O_QKV_H, bfp + O_QKV_L, 3840, 0, 0, nullptr,
            bfp + O_VT_H, bfp + O_VT_L);
        // scores: per bh q[512,64] @ k[512,64]^T * 0.125 -> f32; 64x64, 32KB smem
        hgemm<64,64,0><<<dim3(8, 8, 40), 128, SM64_1STG>>>(
            bfp + O_QKV_H, bfp + O_QKV_L, 3840, 1966080, 64,
            bfp + O_QKV_H + 1280, bfp + O_QKV_L + 1280, 3840, 1966080, 64,
            64, 20, 0.125f, sc, nullptr, nullptr, 512, 5242880, 262144, nullptr, nullptr, nullptr);
        softmax_kernel<<<dim3(512, 40), 256>>>(sc, rel_bias, bfp + O_ATT_H, bfp + O_ATT_L, l == 0 ? 1 : 0);
        // AV: att[512,512] @ vt[64,512]^T -> o split, 64x64 tiles
        hgemm<64,64,1><<<dim3(1, 8, 40), 128, SM64>>>(
            bfp + O_ATT_H, bfp + O_ATT_L, 512, 5242880, 262144,
            bfp + O_VT_H, bfp + O_VT_L, 512, 655360, 32768,
            512, 20, 1.f, nullptr, bfp + O_O_H, bfp + O_O_L, 1280, 655360, 64, nullptr, nullptr, nullptr);
        // x += o @ woT, fused split-store -> xs, 64x64 tiles
        hgemm<64,64,4><<<dim3(20, 16, 1), 128, SM64>>>(
            bfp + O_O_H, bfp + O_O_L, 1280, 0, 0,
            bfp + O_WOT_H + (size_t)l * 1638400, bfp + O_WOT_L + (size_t)l * 1638400, 1280, 0, 0,
            1280, 1, 1.f, x, bfp + O_XS_H, bfp + O_XS_L, 1280, 0, 0, nullptr, nullptr, nullptr);
        // gate = geglu(x @ w1T) fused in epilogue (interleaved W1T), 64x64 tiles
        hgemm<64,64,5><<<dim3(80, 16, 1), 128, SM64>>>(
            bfp + O_XS_H, bfp + O_XS_L, 1280, 0, 0,
            bfp + O_W1T_H + (size_t)l * 6553600, bfp + O_W1T_L + (size_t)l * 6553600, 1280, 0, 0,
            1280, 1, 1.f, nullptr, bfp + O_G_H, bfp + O_G_L, 2560, 0, 0, nullptr, nullptr, nullptr);
        // x += g @ w2T, 64x64 tiles
        hgemm<64,64,2><<<dim3(20, 16, 1), 128, SM64>>>(
            bfp + O_G_H, bfp + O_G_L, 2560, 0, 0,
            bfp + O_W2T_H + (size_t)l * 3276800, bfp + O_W2T_L + (size_t)l * 3276800, 2560, 0, 0,
            2560, 1, 1.f, x, nullptr, nullptr, 1280, 0, 0, nullptr, nullptr, nullptr);
    }

    rmsnorm_kernel<<<T_, 256>>>(x, now, bfp + O_H_H, bfp + O_H_L);
    // classifier, 64x64 tiles
    hgemm<64,64,3><<<dim3(160, 16, 1), 128, SM64>>>(
        bfp + O_H_H, bfp + O_H_L, 1280, 0, 0,
        bfp + O_CLST_H, bfp + O_CLST_L, 1280, 0, 0,
        1280, 1, 1.f, out, nullptr, nullptr, 0, 0, 0, cls_b, nullptr, nullptr);
}

// round 17
// speedup vs baseline: 1.0719x; 1.0310x over previous
#include <cuda_runtime.h>
#include <cuda_bf16.h>
#include <math.h>
#include <stdint.h>

typedef __nv_bfloat16 bf16;

#define B_   2
#define S_   512
#define T_   1024
#define D_   1280
#define H_   20
#define L_   16
#define DI_  2560
#define W1O_ 5120
#define OUT_PER_B 5242880

// ---------------- PTX helpers (baseline, non-'a' features only) ----------------
__device__ __forceinline__ uint32_t smem_u32(const void* p) {
    uint32_t a;
    asm("{ .reg .u64 t; cvta.to.shared.u64 t, %1; cvt.u32.u64 %0, t; }" : "=r"(a) : "l"(p));
    return a;
}
#define SWZ(o) ((o) ^ (((o) >> 3) & 0x70))

#define CPASYNC(dst, src) \
    asm volatile("cp.async.cg.shared.global [%0], [%1], 16;" :: "r"(dst), "l"(src))
#define CPCOMMIT() asm volatile("cp.async.commit_group;" ::: "memory")
#define CPWAIT1()  asm volatile("cp.async.wait_group 1;" ::: "memory")
#define CPWAIT0()  asm volatile("cp.async.wait_group 0;" ::: "memory")

__device__ __forceinline__ void ldsm4(uint32_t* r, uint32_t addr) {
    asm volatile("ldmatrix.sync.aligned.m8n8.x4.shared.b16 {%0,%1,%2,%3}, [%4];"
        : "=r"(r[0]), "=r"(r[1]), "=r"(r[2]), "=r"(r[3]) : "r"(addr));
}
__device__ __forceinline__ uint32_t lds32(uint32_t addr) {
    uint32_t v;
    asm volatile("ld.shared.b32 %0, [%1];" : "=r"(v) : "r"(addr));
    return v;
}
__device__ __forceinline__ void mma_bf16(float* d, const uint32_t* a, const uint32_t* b) {
    asm volatile(
        "mma.sync.aligned.m16n8k16.row.col.f32.bf16.bf16.f32 "
        "{%0,%1,%2,%3}, {%4,%5,%6,%7}, {%8,%9}, {%0,%1,%2,%3};"
        : "+f"(d[0]), "+f"(d[1]), "+f"(d[2]), "+f"(d[3])
        : "r"(a[0]), "r"(a[1]), "r"(a[2]), "r"(a[3]), "r"(b[0]), "r"(b[1]));
}

// ---------------- scratch (bf16 arena) ----------------
#define O_QKVT_H 0ll
#define O_QKVT_L 78643200ll
#define O_WOT_H  157286400ll
#define O_WOT_L  183500800ll
#define O_W1T_H  209715200ll
#define O_W1T_L  314572800ll
#define O_W2T_H  419430400ll
#define O_W2T_L  471859200ll
#define O_CLST_H 524288000ll
#define O_CLST_L 537395200ll
#define O_H_H    550502400ll
#define O_H_L    551813120ll
#define O_QKV_H  553123840ll
#define O_QKV_L  557056000ll
#define O_VT_H   560988160ll
#define O_VT_L   562331648ll
#define O_ATT_H  563675136ll
#define O_ATT_L  574160896ll
#define O_O_H    584646656ll
#define O_O_L    585957376ll
#define O_XS_H   587268096ll
#define O_XS_L   588578816ll
#define O_G_H    589889536ll
#define O_G_L    592510976ll
__device__ bf16 g_bf[595132416ll];
#define OF_X 0
#define OF_S 6553600
__device__ float g_f[17039360];

// ---------------- small kernels ----------------
__global__ void embed_kernel(const float* __restrict__ lat, const float* __restrict__ ew,
                             const float* __restrict__ eb, float* __restrict__ x) {
    int t = blockIdx.y, d = blockIdx.x * 256 + threadIdx.x;
    __shared__ float l[112];
    int b = t >> 9, n = t & 511;
    if (threadIdx.x < 112) l[threadIdx.x] = lat[(size_t)b * 57344 + threadIdx.x * 512 + n];
    __syncthreads();
    float s = eb[d];
    const float* w = ew + (size_t)d * 112;
#pragma unroll 8
    for (int c = 0; c < 112; c++) s += l[c] * w[c];
    x[(size_t)t * D_ + d] = s;
}

__device__ __forceinline__ void spst(float v, bf16* hi, bf16* lo, size_t i) {
    bf16 h = __float2bfloat16(v);
    hi[i] = h;
    lo[i] = __float2bfloat16(v - __bfloat162float(h));
}

__global__ __launch_bounds__(256) void rmsnorm_kernel(const float* __restrict__ x,
                                                      const float* __restrict__ w,
                                                      bf16* __restrict__ oh, bf16* __restrict__ ol) {
    int t = blockIdx.x;
    const float* xr = x + (size_t)t * D_;
    float ss = 0.f;
    for (int i = threadIdx.x; i < D_; i += 256) { float v = xr[i]; ss += v * v; }
    __shared__ float red[8];
    float v = ss;
#pragma unroll
    for (int o = 16; o; o >>= 1) v += __shfl_down_sync(~0u, v, o);
    if ((threadIdx.x & 31) == 0) red[threadIdx.x >> 5] = v;
    __syncthreads();
    if (threadIdx.x == 0) { float r = 0.f; for (int i = 0; i < 8; i++) r += red[i]; red[0] = r; }
    __syncthreads();
    float inv = rsqrtf(red[0] / (float)D_ + 1e-5f);
    size_t b = (size_t)t * D_;
    for (int i = threadIdx.x; i < D_; i += 256) spst(w[i] * (xr[i] * inv), oh, ol, b + i);
}

__device__ __forceinline__ float relbias(const float* __restrict__ rb, int i, int j, int h) {
    int n = i - j, ret = (n < 0) ? 16 : 0, an = (n < 0) ? -n : n, val;
    if (an < 8) val = an;
    else { val = 8 + (int)(logf((float)an * 0.125f) * (8.0f / logf(16.0f))); if (val > 15) val = 15; }
    return rb[(ret + val) * H_ + h];
}

// warp-per-row softmax: 8 rows per CTA, shuffle-only reductions, float4 loads
__global__ __launch_bounds__(256) void softmax_kernel(const float* __restrict__ sc,
                                                      const float* __restrict__ rb,
                                                      bf16* __restrict__ ah, bf16* __restrict__ al,
                                                      int add_bias) {
    int warp = threadIdx.x >> 5, lane = threadIdx.x & 31;
    int i = blockIdx.x * 8 + warp, bh = blockIdx.y, h = bh % H_;
    const float* p = sc + ((size_t)bh * S_ + i) * S_;
    float v[16];
#pragma unroll
    for (int k = 0; k < 4; k++) {
        float4 f = *(const float4*)(p + k * 128 + lane * 4);
        v[k * 4] = f.x; v[k * 4 + 1] = f.y; v[k * 4 + 2] = f.z; v[k * 4 + 3] = f.w;
    }
    if (add_bias) {
#pragma unroll
        for (int k = 0; k < 4; k++)
#pragma unroll
            for (int e = 0; e < 4; e++)
                v[k * 4 + e] += relbias(rb, i, k * 128 + lane * 4 + e, h);
    }
    float m = v[0];
#pragma unroll
    for (int j = 1; j < 16; j++) m = fmaxf(m, v[j]);
#pragma unroll
    for (int o = 16; o; o >>= 1) m = fmaxf(m, __shfl_xor_sync(~0u, m, o));
    float s = 0.f;
#pragma unroll
    for (int j = 0; j < 16; j++) { v[j] = expf(v[j] - m); s += v[j]; }
#pragma unroll
    for (int o = 16; o; o >>= 1) s += __shfl_xor_sync(~0u, s, o);
    float inv = 1.0f / s;
    size_t ob = ((size_t)bh * S_ + i) * S_;
#pragma unroll
    for (int k = 0; k < 4; k++) {
        bf16 h4[4], l4[4];
#pragma unroll
        for (int e = 0; e < 4; e++) {
            float w = v[k * 4 + e] * inv;
            bf16 hh = __float2bfloat16(w);
            h4[e] = hh;
            l4[e] = __float2bfloat16(w - __bfloat162float(hh));
        }
        size_t idx = ob + k * 128 + lane * 4;
        *(uint2*)(ah + idx) = *(uint2*)h4;
        *(uint2*)(al + idx) = *(uint2*)l4;
    }
}

// vectorized fp32 -> split bf16 (uint2 stores)
__global__ void split_kernel(const float* __restrict__ s, bf16* __restrict__ hi, bf16* __restrict__ lo) {
    int i = (blockIdx.x * 256 + threadIdx.x) << 2;
    float4 v = *(const float4*)(s + i);
    bf16 h4[4], l4[4];
    float vv[4] = {v.x, v.y, v.z, v.w};
#pragma unroll
    for (int j = 0; j < 4; j++) {
        bf16 h = __float2bfloat16(vv[j]);
        h4[j] = h;
        l4[j] = __float2bfloat16(vv[j] - __bfloat162float(h));
    }
    *(uint2*)(hi + i) = *(uint2*)h4;
    *(uint2*)(lo + i) = *(uint2*)l4;
}

// transpose+split (vectorized): src fp32 [K][N] (z-batched) -> dst bf16 [N][K] hi/lo.
// tile 64k x 32n; each thread stores 8 contiguous bf16 (uint4) per array.
// di>0: interleave row perm for fused GEGLU (a_j -> 2j, g_j -> 2j+1).
__global__ __launch_bounds__(256) void trans_split(const float* __restrict__ src, long long sZ,
                                                   int K, int N,
                                                   bf16* __restrict__ dh, bf16* __restrict__ dl,
                                                   long long dZ, int di) {
    __shared__ float t[64][33];
    int n0 = blockIdx.x * 32, k0 = blockIdx.y * 64;
    const float* s = src + (size_t)blockIdx.z * sZ;
    int c = threadIdx.x & 31, r0 = threadIdx.x >> 5;
#pragma unroll
    for (int i = 0; i < 8; i++)
        t[r0 + i * 8][c] = s[(size_t)(k0 + r0 + i * 8) * N + n0 + c];
    __syncthreads();
    int n_i = threadIdx.x >> 3, kg = threadIdx.x & 7;
    int n = n0 + n_i;
    int nr = di ? ((n < di) ? 2 * n : 2 * (n - di) + 1) : n;
    size_t base = (size_t)blockIdx.z * dZ + (size_t)nr * K + k0 + kg * 8;
    bf16 h8[8], l8[8];
#pragma unroll
    for (int j = 0; j < 8; j++) {
        float v = t[kg * 8 + j][n_i];
        bf16 h = __float2bfloat16(v);
        h8[j] = h;
        l8[j] = __float2bfloat16(v - __bfloat162float(h));
    }
    *(uint4*)(dh + base) = *(uint4*)h8;
    *(uint4*)(dl + base) = *(uint4*)l8;
}

// ---------------- split-bf16 HMMA GEMM (mma.sync m16n8k16) ----------------
// CTA tile 64x64, K-block 64, 2-stage cp.async pipeline, 128 thr / 4 warps,
// 3 CTAs/SM. R5-proven mainloop: scalar LDS for B fragments (ldmatrix-B
// regressed twice) and pass-inner MMA order hh/hl/lh per accumulator.
// EPI: 0=f32*alpha, 1=split bf16, 2=f32 residual +=, 3=classifier scatter,
//      4=residual += AND split-store, 5=fused GEGLU split-store,
//      6=QKV: split bf16 for q/k cols, direct transposed vt store for v cols
template <int BM, int BN, int EPI>
__global__ __launch_bounds__((BM == 128 ? 256 : 128), (BM == 128 ? 1 : 3)) void hgemm(
    const bf16* __restrict__ Ah, const bf16* __restrict__ Al, long long lda, long long aS1, long long aS2,
    const bf16* __restrict__ Bh, const bf16* __restrict__ Bl, long long ldb, long long bS1, long long bS2,
    int K, int zdiv, float alpha,
    float* __restrict__ Cf, bf16* __restrict__ Ch, bf16* __restrict__ Cl,
    long long ldc, long long cS1, long long cS2, const float* __restrict__ bias,
    bf16* __restrict__ Vh, bf16* __restrict__ Vl) {
    extern __shared__ char sm[];
    constexpr int NT = (BM == 128 ? 256 : 128);
    constexpr int WN_CNT = NT / 64;            // 4 or 2
    constexpr int WN = BN / WN_CNT;            // warp n extent (32 both)
    constexpr int MI = BM / 32;                // m16 tiles per warp (4 or 2)
    constexpr int NREG = WN / 8;               // n8 tiles per warp (4)
    constexpr int RPI = NT / 8;                // rows loaded per iter (32 or 16)
    constexpr int AT = BM * 128;               // A tile bytes
    constexpr int BT = BN * 128;               // B tile bytes
    constexpr int STG = 2 * AT + 2 * BT;

    const int tid = threadIdx.x, lane = tid & 31, wid = tid >> 5;
    const int wm = wid & 1, wn = wid >> 1;
    const int zq = blockIdx.z / zdiv, zr = blockIdx.z - zq * zdiv;
    const int m0 = blockIdx.y * BM, n0 = blockIdx.x * BN;
    const bf16* Ahp = Ah + zq * aS1 + zr * aS2 + (size_t)m0 * lda;
    const bf16* Alp = Al + zq * aS1 + zr * aS2 + (size_t)m0 * lda;
    const bf16* Bhp = Bh + zq * bS1 + zr * bS2 + (size_t)n0 * ldb;
    const bf16* Blp = Bl + zq * bS1 + zr * bS2 + (size_t)n0 * ldb;
    const uint32_t sbase = smem_u32(sm);
    const int KB = K >> 6;

    float acc[MI][NREG][4];
#pragma unroll
    for (int a = 0; a < MI; a++)
#pragma unroll
        for (int b = 0; b < NREG; b++)
#pragma unroll
            for (int c = 0; c < 4; c++) acc[a][b][c] = 0.f;

    const int lr = tid >> 3, lc = tid & 7;

#define LOAD_STAGE(st, kb) do { \
    uint32_t bse = sbase + (st) * STG; \
    long long ko = (long long)(kb) * 64; \
    _Pragma("unroll") \
    for (int i = 0; i < BM / RPI; i++) { \
        int r = lr + i * RPI; \
        uint32_t so = SWZ(r * 128 + lc * 16); \
        CPASYNC(bse + so,      Ahp + (size_t)r * lda + ko + lc * 8); \
        CPASYNC(bse + AT + so, Alp + (size_t)r * lda + ko + lc * 8); \
    } \
    _Pragma("unroll") \
    for (int i = 0; i < BN / RPI; i++) { \
        int r = lr + i * RPI; \
        uint32_t so = SWZ(r * 128 + lc * 16); \
        CPASYNC(bse + 2 * AT + so,      Bhp + (size_t)r * ldb + ko + lc * 8); \
        CPASYNC(bse + 2 * AT + BT + so, Blp + (size_t)r * ldb + ko + lc * 8); \
    } \
    CPCOMMIT(); \
} while (0)

    LOAD_STAGE(0, 0);
    if (KB > 1) LOAD_STAGE(1, 1);

    const int g = lane >> 2, t4 = lane & 3;
    const int arow = wm * (BM / 2) + (lane & 15);
    const int acolb = (lane >> 4) * 16;

    for (int kb = 0; kb < KB; kb++) {
        if (kb + 2 <= KB) CPWAIT1(); else CPWAIT0();
        __syncthreads();
        uint32_t sAh = sbase + (kb & 1) * STG;
        uint32_t sAl = sAh + AT, sBh = sAh + 2 * AT, sBl = sBh + BT;
#pragma unroll
        for (int ks = 0; ks < 4; ks++) {
            uint32_t aH[MI][4], aL[MI][4], bH[NREG][2], bL[NREG][2];
#pragma unroll
            for (int mi = 0; mi < MI; mi++) {
                uint32_t off = SWZ((arow + mi * 16) * 128 + ks * 32 + acolb);
                ldsm4(aH[mi], sAh + off);
                ldsm4(aL[mi], sAl + off);
            }
#pragma unroll
            for (int ni = 0; ni < NREG; ni++) {
                int row = wn * WN + ni * 8 + g;
                uint32_t o0 = SWZ(row * 128 + ks * 32 + t4 * 4);
                uint32_t o1 = SWZ(row * 128 + ks * 32 + t4 * 4 + 16);
                bH[ni][0] = lds32(sBh + o0); bH[ni][1] = lds32(sBh + o1);
                bL[ni][0] = lds32(sBl + o0); bL[ni][1] = lds32(sBl + o1);
            }
#pragma unroll
            for (int mi = 0; mi < MI; mi++)
#pragma unroll
                for (int ni = 0; ni < NREG; ni++) {
                    mma_bf16(acc[mi][ni], aH[mi], bH[ni]);
                    mma_bf16(acc[mi][ni], aH[mi], bL[ni]);
                    mma_bf16(acc[mi][ni], aL[mi], bH[ni]);
                }
        }
        __syncthreads();
        if (kb + 2 < KB) LOAD_STAGE(kb & 1, kb + 2);
    }
#undef LOAD_STAGE

    // epilogue
    const long long coff = zq * cS1 + zr * cS2;
#pragma unroll
    for (int mi = 0; mi < MI; mi++) {
        int r0 = m0 + wm * (BM / 2) + mi * 16 + g;
        int r1 = r0 + 8;
#pragma unroll
        for (int ni = 0; ni < NREG; ni++) {
            int col = n0 + wn * WN + ni * 8 + t4 * 2;
            float v0 = acc[mi][ni][0], v1 = acc[mi][ni][1];
            float v2 = acc[mi][ni][2], v3 = acc[mi][ni][3];
            if (EPI == 0) {
                float2 p0 = {v0 * alpha, v1 * alpha}, p1 = {v2 * alpha, v3 * alpha};
                *(float2*)(Cf + coff + (size_t)r0 * ldc + col) = p0;
                *(float2*)(Cf + coff + (size_t)r1 * ldc + col) = p1;
            } else if (EPI == 1 || EPI == 6) {
                if (EPI == 6 && col >= 2560) {
                    // v columns: write directly into vt[bh][dk][t] (split),
                    // bitwise-identical values to the old vtrans copy path
                    int hh = (col - 2560) >> 6, dk = (col - 2560) & 63;
                    int b0 = r0 >> 9, s0 = r0 & 511;
                    int b1 = r1 >> 9, s1 = r1 & 511;
                    size_t i0 = ((size_t)(b0 * H_ + hh) * 64 + dk) * 512 + s0;
                    size_t i1 = ((size_t)(b1 * H_ + hh) * 64 + dk) * 512 + s1;
                    spst(v0, Vh, Vl, i0);
                    spst(v1, Vh, Vl, i0 + 512);
                    spst(v2, Vh, Vl, i1);
                    spst(v3, Vh, Vl, i1 + 512);
                } else {
                    size_t i0 = coff + (size_t)r0 * ldc + col;
                    size_t i1 = coff + (size_t)r1 * ldc + col;
                    bf16 h0 = __float2bfloat16(v0), h1 = __float2bfloat16(v1);
                    bf16 h2 = __float2bfloat16(v2), h3 = __float2bfloat16(v3);
                    __nv_bfloat162 hh0; hh0.x = h0; hh0.y = h1;
                    __nv_bfloat162 hh1; hh1.x = h2; hh1.y = h3;
                    *(__nv_bfloat162*)(Ch + i0) = hh0;
                    *(__nv_bfloat162*)(Ch + i1) = hh1;
                    __nv_bfloat162 ll0, ll1;
                    ll0.x = __float2bfloat16(v0 - __bfloat162float(h0));
                    ll0.y = __float2bfloat16(v1 - __bfloat162float(h1));
                    ll1.x = __float2bfloat16(v2 - __bfloat162float(h2));
                    ll1.y = __float2bfloat16(v3 - __bfloat162float(h3));
                    *(__nv_bfloat162*)(Cl + i0) = ll0;
                    *(__nv_bfloat162*)(Cl + i1) = ll1;
                }
            } else if (EPI == 2) {
                float* p0 = Cf + coff + (size_t)r0 * ldc + col;
                float* p1 = Cf + coff + (size_t)r1 * ldc + col;
                float2 c0 = *(float2*)p0, c1 = *(float2*)p1;
                c0.x += v0; c0.y += v1; c1.x += v2; c1.y += v3;
                *(float2*)p0 = c0; *(float2*)p1 = c1;
            } else if (EPI == 4) {
                size_t i0 = coff + (size_t)r0 * ldc + col;
                size_t i1 = coff + (size_t)r1 * ldc + col;
                float2 c0 = *(float2*)(Cf + i0), c1 = *(float2*)(Cf + i1);
                c0.x += v0; c0.y += v1; c1.x += v2; c1.y += v3;
                *(float2*)(Cf + i0) = c0; *(float2*)(Cf + i1) = c1;
                bf16 h0 = __float2bfloat16(c0.x), h1 = __float2bfloat16(c0.y);
                bf16 h2 = __float2bfloat16(c1.x), h3 = __float2bfloat16(c1.y);
                __nv_bfloat162 hh0; hh0.x = h0; hh0.y = h1;
                __nv_bfloat162 hh1; hh1.x = h2; hh1.y = h3;
                *(__nv_bfloat162*)(Ch + i0) = hh0;
                *(__nv_bfloat162*)(Ch + i1) = hh1;
                __nv_bfloat162 ll0, ll1;
                ll0.x = __float2bfloat16(c0.x - __bfloat162float(h0));
                ll0.y = __float2bfloat16(c0.y - __bfloat162float(h1));
                ll1.x = __float2bfloat16(c1.x - __bfloat162float(h2));
                ll1.y = __float2bfloat16(c1.y - __bfloat162float(h3));
                *(__nv_bfloat162*)(Cl + i0) = ll0;
                *(__nv_bfloat162*)(Cl + i1) = ll1;
            } else if (EPI == 5) {
                // fused GEGLU: col even = a_j, col odd = g_j, j = col/2
                int j = col >> 1;
                float t0 = tanhf(0.7978845608028654f * (v1 + 0.044715f * v1 * v1 * v1));
                float w0 = v0 * (0.5f * v1 * (1.0f + t0));
                float t1 = tanhf(0.7978845608028654f * (v3 + 0.044715f * v3 * v3 * v3));
                float w1v = v2 * (0.5f * v3 * (1.0f + t1));
                spst(w0, Ch, Cl, (size_t)r0 * ldc + j);
                spst(w1v, Ch, Cl, (size_t)r1 * ldc + j);
            } else if (EPI == 3) {
                int b0 = r0 >> 9, s0 = r0 & 511, b1 = r1 >> 9, s1 = r1 & 511;
#pragma unroll
                for (int e = 0; e < 2; e++) {
                    int cc = col + e;
                    int vv = cc / 10, pp = cc - vv * 10;
                    float bv = bias[cc];
                    Cf[(size_t)b0 * OUT_PER_B + (size_t)vv * 5120 + s0 * 10 + pp] = (e ? v1 : v0) + bv;
                    Cf[(size_t)b1 * OUT_PER_B + (size_t)vv * 5120 + s1 * 10 + pp] = (e ? v3 : v2) + bv;
                }
            }
        }
    }
}

// ---------------- host ----------------
extern "C" void kernel_launch(void* const* d_in, const int* in_sizes, int n_in,
                              void* d_out, int out_size) {
    const float* latents  = (const float*)d_in[0];
    const float* emb_w    = (const float*)d_in[1];
    const float* emb_b    = (const float*)d_in[2];
    const float* norm_w   = (const float*)d_in[3];
    const float* wq       = (const float*)d_in[4];
    const float* wk       = (const float*)d_in[5];
    const float* wv       = (const float*)d_in[6];
    const float* wo       = (const float*)d_in[7];
    const float* w1       = (const float*)d_in[8];
    const float* w2       = (const float*)d_in[9];
    const float* rel_bias = (const float*)d_in[10];
    const float* now      = (const float*)d_in[11];
    const float* cls_w    = (const float*)d_in[12];
    const float* cls_b    = (const float*)d_in[13];
    float* out = (float*)d_out;

    bf16* bfp = nullptr; float* fp = nullptr;
    cudaGetSymbolAddress((void**)&bfp, g_bf);
    cudaGetSymbolAddress((void**)&fp, g_f);

    const int SM64  = 2 * (2 * 64 * 128 + 2 * 64 * 128);    // 65536
    const int SM64_1STG = SM64 / 2;                          // 32768 (KB=1 kernels)
    cudaFuncSetAttribute(hgemm<64,64,0>, cudaFuncAttributeMaxDynamicSharedMemorySize, SM64);
    cudaFuncSetAttribute(hgemm<64,64,1>, cudaFuncAttributeMaxDynamicSharedMemorySize, SM64);
    cudaFuncSetAttribute(hgemm<64,64,2>, cudaFuncAttributeMaxDynamicSharedMemorySize, SM64);
    cudaFuncSetAttribute(hgemm<64,64,3>, cudaFuncAttributeMaxDynamicSharedMemorySize, SM64);
    cudaFuncSetAttribute(hgemm<64,64,4>, cudaFuncAttributeMaxDynamicSharedMemorySize, SM64);
    cudaFuncSetAttribute(hgemm<64,64,5>, cudaFuncAttributeMaxDynamicSharedMemorySize, SM64);
    cudaFuncSetAttribute(hgemm<64,64,6>, cudaFuncAttributeMaxDynamicSharedMemorySize, SM64);

    float* x  = fp + OF_X;
    float* sc = fp + OF_S;

    // weight prep: vectorized transpose [K][N] -> [N][K] + split hi/lo
    trans_split<<<dim3(40, 20, 16), 256>>>(wq, 1638400, 1280, 1280, bfp + O_QKVT_H,           bfp + O_QKVT_L,           4915200, 0);
    trans_split<<<dim3(40, 20, 16), 256>>>(wk, 1638400, 1280, 1280, bfp + O_QKVT_H + 1638400, bfp + O_QKVT_L + 1638400, 4915200, 0);
    trans_split<<<dim3(40, 20, 16), 256>>>(wv, 1638400, 1280, 1280, bfp + O_QKVT_H + 3276800, bfp + O_QKVT_L + 3276800, 4915200, 0);
    trans_split<<<dim3(40, 20, 16), 256>>>(wo, 1638400, 1280, 1280, bfp + O_WOT_H, bfp + O_WOT_L, 1638400, 0);
    trans_split<<<dim3(160, 20, 16), 256>>>(w1, 6553600, 1280, 5120, bfp + O_W1T_H, bfp + O_W1T_L, 6553600, DI_);
    trans_split<<<dim3(40, 40, 16), 256>>>(w2, 3276800, 2560, 1280, bfp + O_W2T_H, bfp + O_W2T_L, 3276800, 0);
    split_kernel<<<12800, 256>>>(cls_w, bfp + O_CLST_H, bfp + O_CLST_L);

    embed_kernel<<<dim3(5, 1024), 256>>>(latents, emb_w, emb_b, x);

    for (int l = 0; l < L_; l++) {
        rmsnorm_kernel<<<T_, 256>>>(x, norm_w + (size_t)l * D_, bfp + O_H_H, bfp + O_H_L);
        // QKV: 64x64 tiles; q/k -> qkv buffer, v -> vt directly (fused vtrans)
        hgemm<64,64,6><<<dim3(60, 16, 1), 128, SM64>>>(
            bfp + O_H_H, bfp + O_H_L, 1280, 0, 0,
            bfp + O_QKVT_H + (size_t)l * 4915200, bfp + O_QKVT_L + (size_t)l * 4915200, 1280, 0, 0,
            1280, 1, 1.f, nullptr, bfp + O_QKV_H, bfp + O_QKV_L, 3840, 0, 0, nullptr,
            bfp + O_VT_H, bfp + O_VT_L);
        // scores: per bh q[512,64] @ k[512,64]^T * 0.125 -> f32; 64x64, 32KB smem
        hgemm<64,64,0><<<dim3(8, 8, 40), 128, SM64_1STG>>>(
            bfp + O_QKV_H, bfp + O_QKV_L, 3840, 1966080, 64,
            bfp + O_QKV_H + 1280, bfp + O_QKV_L + 1280, 3840, 1966080, 64,
            64, 20, 0.125f, sc, nullptr, nullptr, 512, 5242880, 262144, nullptr, nullptr, nullptr);
        // warp-per-row softmax: 2560 CTAs (was 20480), shuffle-only reductions
        softmax_kernel<<<dim3(64, 40), 256>>>(sc, rel_bias, bfp + O_ATT_H, bfp + O_ATT_L, l == 0 ? 1 : 0);
        // AV: att[512,512] @ vt[64,512]^T -> o split, 64x64 tiles
        hgemm<64,64,1><<<dim3(1, 8, 40), 128, SM64>>>(
            bfp + O_ATT_H, bfp + O_ATT_L, 512, 5242880, 262144,
            bfp + O_VT_H, bfp + O_VT_L, 512, 655360, 32768,
            512, 20, 1.f, nullptr, bfp + O_O_H, bfp + O_O_L, 1280, 655360, 64, nullptr, nullptr, nullptr);
        // x += o @ woT, fused split-store -> xs, 64x64 tiles
        hgemm<64,64,4><<<dim3(20, 16, 1), 128, SM64>>>(
            bfp + O_O_H, bfp + O_O_L, 1280, 0, 0,
            bfp + O_WOT_H + (size_t)l * 1638400, bfp + O_WOT_L + (size_t)l * 1638400, 1280, 0, 0,
            1280, 1, 1.f, x, bfp + O_XS_H, bfp + O_XS_L, 1280, 0, 0, nullptr, nullptr, nullptr);
        // gate = geglu(x @ w1T) fused in epilogue (interleaved W1T), 64x64 tiles
        hgemm<64,64,5><<<dim3(80, 16, 1), 128, SM64>>>(
            bfp + O_XS_H, bfp + O_XS_L, 1280, 0, 0,
            bfp + O_W1T_H + (size_t)l * 6553600, bfp + O_W1T_L + (size_t)l * 6553600, 1280, 0, 0,
            1280, 1, 1.f, nullptr, bfp + O_G_H, bfp + O_G_L, 2560, 0, 0, nullptr, nullptr, nullptr);
        // x += g @ w2T, 64x64 tiles
        hgemm<64,64,2><<<dim3(20, 16, 1), 128, SM64>>>(
            bfp + O_G_H, bfp + O_G_L, 2560, 0, 0,
            bfp + O_W2T_H + (size_t)l * 3276800, bfp + O_W2T_L + (size_t)l * 3276800, 2560, 0, 0,
            2560, 1, 1.f, x, nullptr, nullptr, 1280, 0, 0, nullptr, nullptr, nullptr);
    }

    rmsnorm_kernel<<<T_, 256>>>(x, now, bfp + O_H_H, bfp + O_H_L);
    // classifier, 64x64 tiles
    hgemm<64,64,3><<<dim3(160, 16, 1), 128, SM64>>>(
        bfp + O_H_H, bfp + O_H_L, 1280, 0, 0,
        bfp + O_CLST_H, bfp + O_CLST_L, 1280, 0, 0,
        1280, 1, 1.f, out, nullptr, nullptr, 0, 0, 0, cls_b, nullptr, nullptr);
}